// round 2
// baseline (speedup 1.0000x reference)
#include <cuda_runtime.h>

#define SEQ 2048
#define NB 8
#define DM 512
#define DK 64
#define SCALE 0.125f   // 1/sqrt(64)

// Scratch for projected Q, K, V (allocs are forbidden -> device globals)
__device__ float g_Q[NB * SEQ * DK];
__device__ float g_K[NB * SEQ * DK];
__device__ float g_V[NB * SEQ * DK];

// ---------------------------------------------------------------------------
// Projection GEMM: Y[M,64] = X[M,512] @ W[512,64] + b
// BM=128, BN=64, BK=16; 256 threads; each thread computes 8x4 micro-tile.
// (already near the scalar-FMA roofline; unchanged this round)
// ---------------------------------------------------------------------------
__global__ __launch_bounds__(256) void proj_kernel(
    const float* __restrict__ Xq, const float* __restrict__ Xk, const float* __restrict__ Xv,
    const float* __restrict__ Wq, const float* __restrict__ bq,
    const float* __restrict__ Wk, const float* __restrict__ bk,
    const float* __restrict__ Wv, const float* __restrict__ bv)
{
    const float* X; const float* W; const float* bias; float* Y;
    int which = blockIdx.y;
    if (which == 0)      { X = Xq; W = Wq; bias = bq; Y = g_Q; }
    else if (which == 1) { X = Xk; W = Wk; bias = bk; Y = g_K; }
    else                 { X = Xv; W = Wv; bias = bv; Y = g_V; }

    __shared__ float Xs[128][17];
    __shared__ float Ws[16][64];

    const int tid = threadIdx.x;
    const int tx = tid & 15;
    const int ty = tid >> 4;
    const int m0 = blockIdx.x * 128;

    float acc[8][4];
    #pragma unroll
    for (int i = 0; i < 8; i++)
        #pragma unroll
        for (int j = 0; j < 4; j++) acc[i][j] = 0.f;

    for (int kc = 0; kc < DM; kc += 16) {
        #pragma unroll
        for (int i = 0; i < 2; i++) {
            int f4  = i * 256 + tid;
            int row = f4 >> 2;
            int c4  = f4 & 3;
            float4 v = *(const float4*)(X + (size_t)(m0 + row) * DM + kc + c4 * 4);
            Xs[row][c4 * 4 + 0] = v.x;
            Xs[row][c4 * 4 + 1] = v.y;
            Xs[row][c4 * 4 + 2] = v.z;
            Xs[row][c4 * 4 + 3] = v.w;
        }
        {
            int row = tid >> 4;
            int c4  = tid & 15;
            float4 v = *(const float4*)(W + (size_t)(kc + row) * DK + c4 * 4);
            *(float4*)&Ws[row][c4 * 4] = v;
        }
        __syncthreads();

        #pragma unroll
        for (int kk = 0; kk < 16; kk++) {
            float a[8];
            #pragma unroll
            for (int i = 0; i < 8; i++) a[i] = Xs[ty * 8 + i][kk];
            float4 bv4 = *(const float4*)&Ws[kk][tx * 4];
            #pragma unroll
            for (int i = 0; i < 8; i++) {
                acc[i][0] += a[i] * bv4.x;
                acc[i][1] += a[i] * bv4.y;
                acc[i][2] += a[i] * bv4.z;
                acc[i][3] += a[i] * bv4.w;
            }
        }
        __syncthreads();
    }

    float4 bb = *(const float4*)(bias + tx * 4);
    #pragma unroll
    for (int i = 0; i < 8; i++) {
        float4 o;
        o.x = acc[i][0] + bb.x;
        o.y = acc[i][1] + bb.y;
        o.z = acc[i][2] + bb.z;
        o.w = acc[i][3] + bb.w;
        *(float4*)(Y + (size_t)(m0 + ty * 8 + i) * DK + tx * 4) = o;
    }
}

// ---------------------------------------------------------------------------
// Causal flash attention, fp32, QUAD-SPLIT for occupancy:
// Each query row is handled by 4 threads (a lane quad); each owns 16 of the
// 64 head dims. QK^T dot is reduced across the quad with 2x SHFL.XOR.
// Block = 128 threads = 32 query rows. Grid = 64 strips x 8 batches = 512
// blocks, reversed strip order for causal load balance.
// Regs/thread ~85 (vs 255 before) -> occupancy 4.3% -> ~35%+.
// ---------------------------------------------------------------------------
__global__ __launch_bounds__(128) void attn_kernel(float* __restrict__ out)
{
    __shared__ float4 Ks[32][16];   // 32 kv rows x 64 floats
    __shared__ float4 Vs[32][16];

    const int tid = threadIdx.x;
    const int g   = tid & 3;        // dim group: owns floats [g*16, g*16+16)
    const int r   = tid >> 2;       // local query row 0..31
    const int b   = blockIdx.y;
    const int strip = (gridDim.x - 1) - blockIdx.x;   // reversed: long strips first
    const int q0 = strip * 32;
    const int qi = q0 + r;

    const float* Qb = g_Q + (size_t)b * SEQ * DK;
    const float* Kb = g_K + (size_t)b * SEQ * DK;
    const float* Vb = g_V + (size_t)b * SEQ * DK;

    // This thread's 16-dim slice of the q row
    float4 q[4];
    #pragma unroll
    for (int c = 0; c < 4; c++)
        q[c] = *(const float4*)(Qb + (size_t)qi * DK + g * 16 + c * 4);

    float acc[16];
    #pragma unroll
    for (int c = 0; c < 16; c++) acc[c] = 0.f;
    float m = -1e30f, l = 0.f;

    const int ntiles = (q0 + 32) >> 5;   // kv tiles covering [0, q0+31]
    for (int t = 0; t < ntiles; t++) {
        const int k0 = t * 32;
        // Cooperative tile load: 512 float4 each; 4 per thread
        #pragma unroll
        for (int i = 0; i < 4; i++) {
            int f4  = i * 128 + tid;
            int row = f4 >> 4;
            int c4  = f4 & 15;
            Ks[row][c4] = *(const float4*)(Kb + (size_t)(k0 + row) * DK + c4 * 4);
            Vs[row][c4] = *(const float4*)(Vb + (size_t)(k0 + row) * DK + c4 * 4);
        }
        __syncthreads();

        // Scores: each thread does a 16-dim partial dot, quad-reduced via shfl
        float s[32];
        float mt = -1e30f;
        #pragma unroll
        for (int j = 0; j < 32; j++) {
            float d = 0.f;
            #pragma unroll
            for (int c = 0; c < 4; c++) {
                float4 k4 = Ks[j][g * 4 + c];
                d += q[c].x * k4.x + q[c].y * k4.y + q[c].z * k4.z + q[c].w * k4.w;
            }
            d += __shfl_xor_sync(0xFFFFFFFFu, d, 1);
            d += __shfl_xor_sync(0xFFFFFFFFu, d, 2);
            d = (k0 + j <= qi) ? d * SCALE : -1e30f;
            s[j] = d;
            mt = fmaxf(mt, d);
        }

        // Online softmax: single rescale per tile
        const float mnew = fmaxf(m, mt);
        const float corr = __expf(m - mnew);
        l *= corr;
        #pragma unroll
        for (int c = 0; c < 16; c++) acc[c] *= corr;

        #pragma unroll
        for (int j = 0; j < 32; j++) {
            float p = __expf(s[j] - mnew);
            l += p;
            #pragma unroll
            for (int c = 0; c < 4; c++) {
                float4 v4 = Vs[j][g * 4 + c];
                acc[c * 4 + 0] += p * v4.x;
                acc[c * 4 + 1] += p * v4.y;
                acc[c * 4 + 2] += p * v4.z;
                acc[c * 4 + 3] += p * v4.w;
            }
        }
        m = mnew;
        __syncthreads();
    }

    const float inv = 1.f / l;   // l identical across the quad
    float* orow = out + ((size_t)b * SEQ + qi) * DK + g * 16;
    #pragma unroll
    for (int c = 0; c < 4; c++) {
        float4 o;
        o.x = acc[c * 4 + 0] * inv;
        o.y = acc[c * 4 + 1] * inv;
        o.z = acc[c * 4 + 2] * inv;
        o.w = acc[c * 4 + 3] * inv;
        *(float4*)(orow + c * 4) = o;
    }
}

// ---------------------------------------------------------------------------
extern "C" void kernel_launch(void* const* d_in, const int* in_sizes, int n_in,
                              void* d_out, int out_size)
{
    (void)in_sizes; (void)n_in; (void)out_size;
    const float* Xq = (const float*)d_in[0];
    const float* Xk = (const float*)d_in[1];
    const float* Xv = (const float*)d_in[2];
    // d_in[3] = mask (analytically causal; not read)
    const float* Wq = (const float*)d_in[4];
    const float* bq = (const float*)d_in[5];
    const float* Wk = (const float*)d_in[6];
    const float* bk = (const float*)d_in[7];
    const float* Wv = (const float*)d_in[8];
    const float* bv = (const float*)d_in[9];
    float* out = (float*)d_out;

    dim3 pg(NB * SEQ / 128, 3);
    proj_kernel<<<pg, 256>>>(Xq, Xk, Xv, Wq, bq, Wk, bk, Wv, bv);

    dim3 ag(SEQ / 32, NB);     // 64 strips x 8 batches = 512 blocks
    attn_kernel<<<ag, 128>>>(out);
}

// round 3
// speedup vs baseline: 2.6803x; 2.6803x over previous
#include <cuda_runtime.h>

#define SEQ 2048
#define NB 8
#define DM 512
#define DK 64
#define SCALE 0.125f   // 1/sqrt(64)

// Scratch for projected Q, K, V (allocs are forbidden -> device globals)
__device__ float g_Q[NB * SEQ * DK];
__device__ float g_K[NB * SEQ * DK];
__device__ float g_V[NB * SEQ * DK];

// ---------------------------------------------------------------------------
// Projection GEMM: Y[M,64] = X[M,512] @ W[512,64] + b
// Measured at ~100% of scalar-FMA roofline; unchanged.
// ---------------------------------------------------------------------------
__global__ __launch_bounds__(256) void proj_kernel(
    const float* __restrict__ Xq, const float* __restrict__ Xk, const float* __restrict__ Xv,
    const float* __restrict__ Wq, const float* __restrict__ bq,
    const float* __restrict__ Wk, const float* __restrict__ bk,
    const float* __restrict__ Wv, const float* __restrict__ bv)
{
    const float* X; const float* W; const float* bias; float* Y;
    int which = blockIdx.y;
    if (which == 0)      { X = Xq; W = Wq; bias = bq; Y = g_Q; }
    else if (which == 1) { X = Xk; W = Wk; bias = bk; Y = g_K; }
    else                 { X = Xv; W = Wv; bias = bv; Y = g_V; }

    __shared__ float Xs[128][17];
    __shared__ float Ws[16][64];

    const int tid = threadIdx.x;
    const int tx = tid & 15;
    const int ty = tid >> 4;
    const int m0 = blockIdx.x * 128;

    float acc[8][4];
    #pragma unroll
    for (int i = 0; i < 8; i++)
        #pragma unroll
        for (int j = 0; j < 4; j++) acc[i][j] = 0.f;

    for (int kc = 0; kc < DM; kc += 16) {
        #pragma unroll
        for (int i = 0; i < 2; i++) {
            int f4  = i * 256 + tid;
            int row = f4 >> 2;
            int c4  = f4 & 3;
            float4 v = *(const float4*)(X + (size_t)(m0 + row) * DM + kc + c4 * 4);
            Xs[row][c4 * 4 + 0] = v.x;
            Xs[row][c4 * 4 + 1] = v.y;
            Xs[row][c4 * 4 + 2] = v.z;
            Xs[row][c4 * 4 + 3] = v.w;
        }
        {
            int row = tid >> 4;
            int c4  = tid & 15;
            float4 v = *(const float4*)(W + (size_t)(kc + row) * DK + c4 * 4);
            *(float4*)&Ws[row][c4 * 4] = v;
        }
        __syncthreads();

        #pragma unroll
        for (int kk = 0; kk < 16; kk++) {
            float a[8];
            #pragma unroll
            for (int i = 0; i < 8; i++) a[i] = Xs[ty * 8 + i][kk];
            float4 bv4 = *(const float4*)&Ws[kk][tx * 4];
            #pragma unroll
            for (int i = 0; i < 8; i++) {
                acc[i][0] += a[i] * bv4.x;
                acc[i][1] += a[i] * bv4.y;
                acc[i][2] += a[i] * bv4.z;
                acc[i][3] += a[i] * bv4.w;
            }
        }
        __syncthreads();
    }

    float4 bb = *(const float4*)(bias + tx * 4);
    #pragma unroll
    for (int i = 0; i < 8; i++) {
        float4 o;
        o.x = acc[i][0] + bb.x;
        o.y = acc[i][1] + bb.y;
        o.z = acc[i][2] + bb.z;
        o.w = acc[i][3] + bb.w;
        *(float4*)(Y + (size_t)(m0 + ty * 8 + i) * DK + tx * 4) = o;
    }
}

// ---------------------------------------------------------------------------
// Register-tiled causal flash attention.
// Block: 256 threads (ty 0..15 x tx 0..15). BM=64 queries, BN=64 kv / tile.
// Thread owns: score tile rows {ty*4..+3} x cols {tx, 16+tx, 32+tx, 48+tx},
//              output tile rows {ty*4..+3} x dims {tx*4..+3}.
// SMEM (dynamic, 48KB):
//   Qct[16][64] float4  - Q dim-chunk-transposed: [d4][row]  (broadcast reads)
//   Kct[16][64] float4  - K dim-chunk-transposed: [d4][col]  (lane-consecutive)
//        aliased by Ps[64][64] float, XOR-swizzled (chunk = ty^(j&15))
//   Vs [64][16] float4  - V natural: [row][d4]               (lane-consecutive)
// ---------------------------------------------------------------------------
__global__ __launch_bounds__(256) void attn_kernel(float* __restrict__ out)
{
    extern __shared__ float smemf[];
    float4* Qct = (float4*)smemf;     // 1024 float4 = 16KB
    float4* Kct = Qct + 1024;         // 1024 float4 = 16KB (aliased by Ps)
    float*  Ps  = (float*)Kct;
    float4* Vs  = Kct + 1024;         // 1024 float4 = 16KB

    const int tid = threadIdx.x;
    const int tx  = tid & 15;
    const int ty  = tid >> 4;
    const int ty4 = ty * 4;

    // --- makespan-balanced work mapping (bids b and b+148 share an SM) ---
    int bid = blockIdx.x;
    int rank;
    if (bid < 108)      rank = 40 + bid;          // paired slot, first member
    else if (bid < 148) rank = bid - 108;         // solo SMs get the 40 biggest
    else                rank = 255 - (bid - 148); // paired slot, second member
    const int strip = 31 - (rank >> 3);           // rank 0 = biggest strip
    const int b     = rank & 7;
    const int q0    = strip * 64;

    const float* Qb = g_Q + (size_t)b * SEQ * DK;
    const float* Kb = g_K + (size_t)b * SEQ * DK;
    const float* Vb = g_V + (size_t)b * SEQ * DK;

    // Load Q tile (once), dim-chunk-transposed: Qct[d4][row]
    #pragma unroll
    for (int i = 0; i < 4; i++) {
        int idx = i * 256 + tid;
        int row = idx >> 4, c4 = idx & 15;
        Qct[c4 * 64 + row] = *((const float4*)(Qb + (size_t)(q0 + row) * DK) + c4);
    }

    float4 acc[4];
    #pragma unroll
    for (int i = 0; i < 4; i++) acc[i] = make_float4(0.f, 0.f, 0.f, 0.f);
    float m[4] = {-1e30f, -1e30f, -1e30f, -1e30f};
    float l[4] = {0.f, 0.f, 0.f, 0.f};

    const int ntiles = strip + 1;
    for (int t = 0; t < ntiles; t++) {
        const int k0 = t * 64;
        __syncthreads();   // (A) prev GEMM2 done; safe to overwrite Kct(=Ps), Vs

        // Load K (transposed) and V (natural) tiles
        #pragma unroll
        for (int i = 0; i < 4; i++) {
            int idx = i * 256 + tid;
            int row = idx >> 4, c4 = idx & 15;
            Kct[c4 * 64 + row] = *((const float4*)(Kb + (size_t)(k0 + row) * DK) + c4);
            Vs[row * 16 + c4]  = *((const float4*)(Vb + (size_t)(k0 + row) * DK) + c4);
        }
        __syncthreads();   // (B) tiles ready

        // ---- GEMM1: S = Q K^T (4x4 per thread) ----
        float s[4][4];
        #pragma unroll
        for (int i = 0; i < 4; i++)
            #pragma unroll
            for (int j = 0; j < 4; j++) s[i][j] = 0.f;

        #pragma unroll 4
        for (int d4 = 0; d4 < 16; d4++) {
            float4 q4[4], k4[4];
            #pragma unroll
            for (int i = 0; i < 4; i++) q4[i] = Qct[d4 * 64 + ty4 + i];    // broadcast
            #pragma unroll
            for (int j = 0; j < 4; j++) k4[j] = Kct[d4 * 64 + j * 16 + tx]; // consecutive
            #pragma unroll
            for (int i = 0; i < 4; i++)
                #pragma unroll
                for (int j = 0; j < 4; j++) {
                    s[i][j] += q4[i].x * k4[j].x + q4[i].y * k4[j].y
                             + q4[i].z * k4[j].z + q4[i].w * k4[j].w;
                }
        }

        // ---- softmax part 1: scale, mask (diagonal tile only), row max ----
        const bool last = (t == ntiles - 1);
        float mt[4] = {-1e30f, -1e30f, -1e30f, -1e30f};
        #pragma unroll
        for (int i = 0; i < 4; i++)
            #pragma unroll
            for (int j = 0; j < 4; j++) {
                float sv = s[i][j] * SCALE;
                if (last && (k0 + j * 16 + tx > q0 + ty4 + i)) sv = -1e30f;
                s[i][j] = sv;
                mt[i] = fmaxf(mt[i], sv);
            }
        #pragma unroll
        for (int i = 0; i < 4; i++)
            #pragma unroll
            for (int o = 1; o < 16; o <<= 1)
                mt[i] = fmaxf(mt[i], __shfl_xor_sync(0xffffffffu, mt[i], o));

        float corr[4];
        #pragma unroll
        for (int i = 0; i < 4; i++) {
            float mnew = fmaxf(m[i], mt[i]);
            corr[i] = __expf(m[i] - mnew);
            m[i] = mnew;
        }
        __syncthreads();   // (C) all threads done reading Kct; Ps writes may begin

        // ---- softmax part 2: p = exp(s-m), write Ps (swizzled), row sums ----
        const int swc = (ty ^ tx) << 2;   // swizzled float offset for writes
        #pragma unroll
        for (int i = 0; i < 4; i++) {
            float rs = 0.f;
            #pragma unroll
            for (int j = 0; j < 4; j++) {
                float p = __expf(s[i][j] - m[i]);
                rs += p;
                Ps[(j * 16 + tx) * 64 + swc + i] = p;
            }
            #pragma unroll
            for (int o = 1; o < 16; o <<= 1)
                rs += __shfl_xor_sync(0xffffffffu, rs, o);
            l[i] = l[i] * corr[i] + rs;
            acc[i].x *= corr[i]; acc[i].y *= corr[i];
            acc[i].z *= corr[i]; acc[i].w *= corr[i];
        }
        __syncthreads();   // (D) Ps visible

        // ---- GEMM2: O += P V (rows ty4..+3, dims tx*4..+3) ----
        #pragma unroll 8
        for (int j = 0; j < 64; j++) {
            float4 v4 = Vs[j * 16 + tx];                                   // consecutive
            float4 pv = *(const float4*)&Ps[j * 64 + ((ty ^ (j & 15)) << 2)]; // broadcast
            acc[0].x += pv.x * v4.x; acc[0].y += pv.x * v4.y;
            acc[0].z += pv.x * v4.z; acc[0].w += pv.x * v4.w;
            acc[1].x += pv.y * v4.x; acc[1].y += pv.y * v4.y;
            acc[1].z += pv.y * v4.z; acc[1].w += pv.y * v4.w;
            acc[2].x += pv.z * v4.x; acc[2].y += pv.z * v4.y;
            acc[2].z += pv.z * v4.z; acc[2].w += pv.z * v4.w;
            acc[3].x += pv.w * v4.x; acc[3].y += pv.w * v4.y;
            acc[3].z += pv.w * v4.z; acc[3].w += pv.w * v4.w;
        }
    }

    // ---- epilogue ----
    #pragma unroll
    for (int i = 0; i < 4; i++) {
        float inv = 1.f / l[i];
        float4 o;
        o.x = acc[i].x * inv; o.y = acc[i].y * inv;
        o.z = acc[i].z * inv; o.w = acc[i].w * inv;
        *(float4*)(out + ((size_t)b * SEQ + q0 + ty4 + i) * DK + tx * 4) = o;
    }
}

// ---------------------------------------------------------------------------
extern "C" void kernel_launch(void* const* d_in, const int* in_sizes, int n_in,
                              void* d_out, int out_size)
{
    (void)in_sizes; (void)n_in; (void)out_size;
    const float* Xq = (const float*)d_in[0];
    const float* Xk = (const float*)d_in[1];
    const float* Xv = (const float*)d_in[2];
    // d_in[3] = mask (analytically causal; not read)
    const float* Wq = (const float*)d_in[4];
    const float* bq = (const float*)d_in[5];
    const float* Wk = (const float*)d_in[6];
    const float* bk = (const float*)d_in[7];
    const float* Wv = (const float*)d_in[8];
    const float* bv = (const float*)d_in[9];
    float* out = (float*)d_out;

    dim3 pg(NB * SEQ / 128, 3);
    proj_kernel<<<pg, 256>>>(Xq, Xk, Xv, Wq, bq, Wk, bk, Wv, bv);

    attn_kernel<<<256, 256, 49152>>>(out);
}

// round 5
// speedup vs baseline: 5.3736x; 2.0049x over previous
#include <cuda_runtime.h>
#include <cuda_bf16.h>
#include <cstdint>

#define SEQ 2048
#define NB 8
#define DM 512
#define DK 64
#define SCALE 0.125f   // 1/sqrt(64)

// bf16 hi/lo split Q,K,V; 2 bf16 packed per uint32 (low = even col)
__device__ uint32_t g_Qh[NB * SEQ * DK / 2], g_Ql[NB * SEQ * DK / 2];
__device__ uint32_t g_Kh[NB * SEQ * DK / 2], g_Kl[NB * SEQ * DK / 2];
__device__ uint32_t g_Vh[NB * SEQ * DK / 2], g_Vl[NB * SEQ * DK / 2];

#define SW128(x) ((x) ^ (((x) >> 3) & 0x70))

__device__ __forceinline__ uint32_t smem_u32(const void* p) {
    uint32_t a;
    asm("{ .reg .u64 t; cvta.to.shared.u64 t, %1; cvt.u32.u64 %0, t; }" : "=r"(a) : "l"(p));
    return a;
}

// split a,b (f32) -> packed bf16x2 hi parts and packed bf16x2 residuals
__device__ __forceinline__ void split2(float a, float b, uint32_t& h, uint32_t& l) {
    float ah = __bfloat162float(__float2bfloat16(a));
    float bh = __bfloat162float(__float2bfloat16(b));
    __nv_bfloat162 H = __floats2bfloat162_rn(a, b);        // low = a
    __nv_bfloat162 L = __floats2bfloat162_rn(a - ah, b - bh);
    h = *(uint32_t*)&H;
    l = *(uint32_t*)&L;
}

#define LDSM4(r0, r1, r2, r3, a) \
    asm volatile("ldmatrix.sync.aligned.m8n8.x4.shared.b16 {%0,%1,%2,%3}, [%4];" \
                 : "=r"(r0), "=r"(r1), "=r"(r2), "=r"(r3) : "r"(a))
#define LDSM4T(r0, r1, r2, r3, a) \
    asm volatile("ldmatrix.sync.aligned.m8n8.x4.trans.shared.b16 {%0,%1,%2,%3}, [%4];" \
                 : "=r"(r0), "=r"(r1), "=r"(r2), "=r"(r3) : "r"(a))
#define MMA(c, a, b0, b1) \
    asm volatile("mma.sync.aligned.m16n8k16.row.col.f32.bf16.bf16.f32 " \
                 "{%0,%1,%2,%3},{%4,%5,%6,%7},{%8,%9},{%0,%1,%2,%3};" \
                 : "+f"((c)[0]), "+f"((c)[1]), "+f"((c)[2]), "+f"((c)[3]) \
                 : "r"((a)[0]), "r"((a)[1]), "r"((a)[2]), "r"((a)[3]), "r"(b0), "r"(b1))

// ---------------------------------------------------------------------------
// Projection GEMM via mma.sync bf16 hi/lo: Y[M,64] = X[M,512] @ W[512,64] + b
// 256 threads / 8 warps. BM=128 (16 rows/warp), BN=64, BK=64 (8 chunks).
// Emits bf16 hi/lo packed outputs (Q pre-scaled by 1/sqrt(dk)).
// ---------------------------------------------------------------------------
__global__ __launch_bounds__(256) void proj_kernel(
    const float* __restrict__ Xq, const float* __restrict__ Xk, const float* __restrict__ Xv,
    const float* __restrict__ Wq, const float* __restrict__ bq,
    const float* __restrict__ Wk, const float* __restrict__ bk,
    const float* __restrict__ Wv, const float* __restrict__ bv)
{
    __shared__ __align__(128) unsigned char sm[49152];
    // XH @0 (16KB), XL @16384, WH @32768 (8KB), WL @40960

    const float* X; const float* W; const float* bias;
    uint32_t* Yh; uint32_t* Yl; float osc;
    const int which = blockIdx.y;
    if (which == 0)      { X = Xq; W = Wq; bias = bq; Yh = g_Qh; Yl = g_Ql; osc = SCALE; }
    else if (which == 1) { X = Xk; W = Wk; bias = bk; Yh = g_Kh; Yl = g_Kl; osc = 1.f; }
    else                 { X = Xv; W = Wv; bias = bv; Yh = g_Vh; Yl = g_Vl; osc = 1.f; }

    const int tid = threadIdx.x, lane = tid & 31, wid = tid >> 5;
    const int m0 = blockIdx.x * 128, mw = wid * 16;
    const uint32_t sb = smem_u32(sm);
    const int r8 = lane & 7, sub = lane >> 3;

    float acc[8][4];
    #pragma unroll
    for (int n = 0; n < 8; n++)
        #pragma unroll
        for (int e = 0; e < 4; e++) acc[n][e] = 0.f;

    for (int c = 0; c < 8; c++) {
        __syncthreads();
        {   // X chunk: 128 rows x 64 cols -> XH/XL (SW128, 128B rows)
            const int row = tid >> 1, half = tid & 1;
            const float4* src = (const float4*)(X + (size_t)(m0 + row) * DM + c * 64 + half * 32);
            #pragma unroll
            for (int g4 = 0; g4 < 4; g4++) {
                float4 f0 = src[g4 * 2], f1 = src[g4 * 2 + 1];
                uint4 h, l;
                split2(f0.x, f0.y, h.x, l.x); split2(f0.z, f0.w, h.y, l.y);
                split2(f1.x, f1.y, h.z, l.z); split2(f1.z, f1.w, h.w, l.w);
                const uint32_t off = SW128(row * 128 + half * 64 + g4 * 16);
                *(uint4*)(sm + off)         = h;
                *(uint4*)(sm + 16384 + off) = l;
            }
        }
        {   // W chunk: 64 k-rows x 64 n-cols -> WH/WL
            const int row = tid >> 2, qq = tid & 3;
            const float4* src = (const float4*)(W + (size_t)(c * 64 + row) * 64 + qq * 16);
            #pragma unroll
            for (int g4 = 0; g4 < 2; g4++) {
                float4 f0 = src[g4 * 2], f1 = src[g4 * 2 + 1];
                uint4 h, l;
                split2(f0.x, f0.y, h.x, l.x); split2(f0.z, f0.w, h.y, l.y);
                split2(f1.x, f1.y, h.z, l.z); split2(f1.z, f1.w, h.w, l.w);
                const uint32_t off = SW128(row * 128 + qq * 32 + g4 * 16);
                *(uint4*)(sm + 32768 + off) = h;
                *(uint4*)(sm + 40960 + off) = l;
            }
        }
        __syncthreads();

        // A fragments for this warp (4 k-steps, hi/lo)
        uint32_t ah[4][4], al[4][4];
        #pragma unroll
        for (int kk = 0; kk < 4; kk++) {
            const int row = mw + r8 + ((sub & 1) << 3);
            const int byt = kk * 32 + ((sub >> 1) << 4);
            const uint32_t off = SW128(row * 128 + byt);
            LDSM4(ah[kk][0], ah[kk][1], ah[kk][2], ah[kk][3], sb + off);
            LDSM4(al[kk][0], al[kk][1], al[kk][2], al[kk][3], sb + 16384 + off);
        }
        // B (W^T) via ldmatrix.trans + MMAs
        #pragma unroll
        for (int j = 0; j < 4; j++) {
            #pragma unroll
            for (int kk = 0; kk < 4; kk++) {
                const int row = kk * 16 + r8 + ((sub & 1) << 3);
                const int byt = j * 32 + ((sub >> 1) << 4);
                const uint32_t off = SW128(row * 128 + byt);
                uint32_t h0, h1, h2, h3, u0, u1, u2, u3;
                LDSM4T(h0, h1, h2, h3, sb + 32768 + off);
                LDSM4T(u0, u1, u2, u3, sb + 40960 + off);
                MMA(acc[2 * j],     ah[kk], h0, h1);
                MMA(acc[2 * j],     al[kk], h0, h1);
                MMA(acc[2 * j],     ah[kk], u0, u1);
                MMA(acc[2 * j + 1], ah[kk], h2, h3);
                MMA(acc[2 * j + 1], al[kk], h2, h3);
                MMA(acc[2 * j + 1], ah[kk], u2, u3);
            }
        }
    }

    // epilogue: bias, optional scale, split -> packed hi/lo bf16
    const int g = lane >> 2, cb = (lane & 3) * 2;
    #pragma unroll
    for (int n = 0; n < 8; n++) {
        const int col = n * 8 + cb;
        const float b0 = bias[col], b1 = bias[col + 1];
        const size_t r0 = (size_t)(m0 + mw + g), r1 = r0 + 8;
        uint32_t h, l;
        split2((acc[n][0] + b0) * osc, (acc[n][1] + b1) * osc, h, l);
        Yh[r0 * 32 + (col >> 1)] = h;  Yl[r0 * 32 + (col >> 1)] = l;
        split2((acc[n][2] + b0) * osc, (acc[n][3] + b1) * osc, h, l);
        Yh[r1 * 32 + (col >> 1)] = h;  Yl[r1 * 32 + (col >> 1)] = l;
    }
}

// ---------------------------------------------------------------------------
// Causal flash attention via mma.sync bf16 hi/lo.
// 128 threads / 4 warps; BM=64 q-rows (16/warp), BN=64 kv per tile.
// S accumulators -> softmax in regs -> repacked as A-frags for P@V (no SMEM P).
// SMEM 48KB: QH@0 QL@8K KH@16K KL@24K VH@32K VL@40K, all 64x128B SW128.
// ---------------------------------------------------------------------------
__global__ __launch_bounds__(128) void attn_kernel(float* __restrict__ out)
{
    __shared__ __align__(128) unsigned char sm[49152];

    const int tid = threadIdx.x, lane = tid & 31, wid = tid >> 5;
    const int r8 = lane & 7, sub = lane >> 3;

    // balanced causal schedule (bids b and b+148 share an SM)
    const int bid = blockIdx.x;
    int rank;
    if (bid < 108)      rank = 40 + bid;
    else if (bid < 148) rank = bid - 108;
    else                rank = 255 - (bid - 148);
    const int strip = 31 - (rank >> 3);
    const int b     = rank & 7;
    const int q0    = strip * 64;
    const int base  = b * SEQ;
    const uint32_t sb = smem_u32(sm);

    // ---- Q tile (rows q0..q0+63) -> SMEM, then A-fragments (kept in regs) ----
    {
        const int row = tid >> 1, half = tid & 1;
        const uint4* sh = (const uint4*)(g_Qh + (size_t)(base + q0 + row) * 32 + half * 16);
        const uint4* sl = (const uint4*)(g_Ql + (size_t)(base + q0 + row) * 32 + half * 16);
        #pragma unroll
        for (int g4 = 0; g4 < 4; g4++) {
            const uint32_t off = SW128(row * 128 + half * 64 + g4 * 16);
            *(uint4*)(sm + off)        = sh[g4];
            *(uint4*)(sm + 8192 + off) = sl[g4];
        }
    }
    __syncthreads();
    uint32_t qh[4][4], ql[4][4];
    #pragma unroll
    for (int kk = 0; kk < 4; kk++) {
        const int row = wid * 16 + r8 + ((sub & 1) << 3);
        const int byt = kk * 32 + ((sub >> 1) << 4);
        const uint32_t off = SW128(row * 128 + byt);
        LDSM4(qh[kk][0], qh[kk][1], qh[kk][2], qh[kk][3], sb + off);
        LDSM4(ql[kk][0], ql[kk][1], ql[kk][2], ql[kk][3], sb + 8192 + off);
    }

    float od[8][4];
    #pragma unroll
    for (int n = 0; n < 8; n++)
        #pragma unroll
        for (int e = 0; e < 4; e++) od[n][e] = 0.f;
    float m0v = -1e30f, m1v = -1e30f, l0 = 0.f, l1 = 0.f;

    const int ntiles = strip + 1;
    for (int t = 0; t < ntiles; t++) {
        const int k0 = t * 64;
        __syncthreads();   // prev-iter fragment reads done before overwrite
        {   // copy K/V hi/lo tiles (swizzled)
            const int row = tid >> 1, half = tid & 1;
            const size_t gr = (size_t)(base + k0 + row) * 32 + half * 16;
            const uint4* kh = (const uint4*)(g_Kh + gr);
            const uint4* kl = (const uint4*)(g_Kl + gr);
            const uint4* vh = (const uint4*)(g_Vh + gr);
            const uint4* vl = (const uint4*)(g_Vl + gr);
            #pragma unroll
            for (int g4 = 0; g4 < 4; g4++) {
                const uint32_t off = SW128(row * 128 + half * 64 + g4 * 16);
                *(uint4*)(sm + 16384 + off) = kh[g4];
                *(uint4*)(sm + 24576 + off) = kl[g4];
                *(uint4*)(sm + 32768 + off) = vh[g4];
                *(uint4*)(sm + 40960 + off) = vl[g4];
            }
        }
        __syncthreads();

        // ---- GEMM1: S = Qh*Kh + Ql*Kh + Qh*Kl ----
        float sc[8][4];
        #pragma unroll
        for (int n = 0; n < 8; n++)
            #pragma unroll
            for (int e = 0; e < 4; e++) sc[n][e] = 0.f;

        #pragma unroll
        for (int j = 0; j < 4; j++) {
            #pragma unroll
            for (int kk = 0; kk < 4; kk++) {
                const int row = j * 16 + r8 + ((sub & 2) << 2);
                const int byt = kk * 32 + ((sub & 1) << 4);
                const uint32_t off = SW128(row * 128 + byt);
                uint32_t h0, h1, h2, h3, u0, u1, u2, u3;
                LDSM4(h0, h1, h2, h3, sb + 16384 + off);
                LDSM4(u0, u1, u2, u3, sb + 24576 + off);
                MMA(sc[2 * j],     qh[kk], h0, h1);
                MMA(sc[2 * j],     ql[kk], h0, h1);
                MMA(sc[2 * j],     qh[kk], u0, u1);
                MMA(sc[2 * j + 1], qh[kk], h2, h3);
                MMA(sc[2 * j + 1], ql[kk], h2, h3);
                MMA(sc[2 * j + 1], qh[kk], u2, u3);
            }
        }

        // ---- mask (diagonal tile only; scale pre-folded into Q) ----
        if (t == ntiles - 1) {
            const int cb = (lane & 3) * 2, rl = wid * 16 + (lane >> 2);
            #pragma unroll
            for (int n = 0; n < 8; n++) {
                const int c0 = n * 8 + cb;
                if (c0     > rl)     sc[n][0] = -1e30f;
                if (c0 + 1 > rl)     sc[n][1] = -1e30f;
                if (c0     > rl + 8) sc[n][2] = -1e30f;
                if (c0 + 1 > rl + 8) sc[n][3] = -1e30f;
            }
        }

        // ---- online softmax (rows: lane>>2 and +8) ----
        float rm0 = -1e30f, rm1 = -1e30f;
        #pragma unroll
        for (int n = 0; n < 8; n++) {
            rm0 = fmaxf(rm0, fmaxf(sc[n][0], sc[n][1]));
            rm1 = fmaxf(rm1, fmaxf(sc[n][2], sc[n][3]));
        }
        rm0 = fmaxf(rm0, __shfl_xor_sync(0xffffffffu, rm0, 1));
        rm0 = fmaxf(rm0, __shfl_xor_sync(0xffffffffu, rm0, 2));
        rm1 = fmaxf(rm1, __shfl_xor_sync(0xffffffffu, rm1, 1));
        rm1 = fmaxf(rm1, __shfl_xor_sync(0xffffffffu, rm1, 2));
        const float nm0 = fmaxf(m0v, rm0), nm1 = fmaxf(m1v, rm1);
        const float cor0 = __expf(m0v - nm0), cor1 = __expf(m1v - nm1);
        m0v = nm0; m1v = nm1;

        float rs0 = 0.f, rs1 = 0.f;
        #pragma unroll
        for (int n = 0; n < 8; n++) {
            sc[n][0] = __expf(sc[n][0] - nm0); rs0 += sc[n][0];
            sc[n][1] = __expf(sc[n][1] - nm0); rs0 += sc[n][1];
            sc[n][2] = __expf(sc[n][2] - nm1); rs1 += sc[n][2];
            sc[n][3] = __expf(sc[n][3] - nm1); rs1 += sc[n][3];
        }
        rs0 += __shfl_xor_sync(0xffffffffu, rs0, 1);
        rs0 += __shfl_xor_sync(0xffffffffu, rs0, 2);
        rs1 += __shfl_xor_sync(0xffffffffu, rs1, 1);
        rs1 += __shfl_xor_sync(0xffffffffu, rs1, 2);
        l0 = l0 * cor0 + rs0;
        l1 = l1 * cor1 + rs1;
        #pragma unroll
        for (int n = 0; n < 8; n++) {
            od[n][0] *= cor0; od[n][1] *= cor0;
            od[n][2] *= cor1; od[n][3] *= cor1;
        }

        // ---- pack P accumulators as A-fragments (FA-2 layout identity) ----
        uint32_t ph[4][4], pl[4][4];
        #pragma unroll
        for (int kk = 0; kk < 4; kk++) {
            split2(sc[2 * kk][0],     sc[2 * kk][1],     ph[kk][0], pl[kk][0]);
            split2(sc[2 * kk][2],     sc[2 * kk][3],     ph[kk][1], pl[kk][1]);
            split2(sc[2 * kk + 1][0], sc[2 * kk + 1][1], ph[kk][2], pl[kk][2]);
            split2(sc[2 * kk + 1][2], sc[2 * kk + 1][3], ph[kk][3], pl[kk][3]);
        }

        // ---- GEMM2: O += Ph*Vh + Pl*Vh + Ph*Vl  (V via ldmatrix.trans) ----
        #pragma unroll
        for (int j = 0; j < 4; j++) {
            #pragma unroll
            for (int kk = 0; kk < 4; kk++) {
                const int row = kk * 16 + r8 + ((sub & 1) << 3);
                const int byt = j * 32 + ((sub >> 1) << 4);
                const uint32_t off = SW128(row * 128 + byt);
                uint32_t h0, h1, h2, h3, u0, u1, u2, u3;
                LDSM4T(h0, h1, h2, h3, sb + 32768 + off);
                LDSM4T(u0, u1, u2, u3, sb + 40960 + off);
                MMA(od[2 * j],     ph[kk], h0, h1);
                MMA(od[2 * j],     pl[kk], h0, h1);
                MMA(od[2 * j],     ph[kk], u0, u1);
                MMA(od[2 * j + 1], ph[kk], h2, h3);
                MMA(od[2 * j + 1], pl[kk], h2, h3);
                MMA(od[2 * j + 1], ph[kk], u2, u3);
            }
        }
    }

    // ---- epilogue: normalize and store f32 ----
    const float inv0 = 1.f / l0, inv1 = 1.f / l1;
    const int g = lane >> 2, cb = (lane & 3) * 2;
    const size_t r0 = (size_t)b * SEQ + q0 + wid * 16 + g, r1 = r0 + 8;
    #pragma unroll
    for (int n = 0; n < 8; n++) {
        float2 o0 = make_float2(od[n][0] * inv0, od[n][1] * inv0);
        float2 o1 = make_float2(od[n][2] * inv1, od[n][3] * inv1);
        *(float2*)(out + r0 * DK + n * 8 + cb) = o0;
        *(float2*)(out + r1 * DK + n * 8 + cb) = o1;
    }
}

// ---------------------------------------------------------------------------
extern "C" void kernel_launch(void* const* d_in, const int* in_sizes, int n_in,
                              void* d_out, int out_size)
{
    (void)in_sizes; (void)n_in; (void)out_size;
    const float* Xq = (const float*)d_in[0];
    const float* Xk = (const float*)d_in[1];
    const float* Xv = (const float*)d_in[2];
    // d_in[3] = mask (analytically causal; not read)
    const float* Wq = (const float*)d_in[4];
    const float* bq = (const float*)d_in[5];
    const float* Wk = (const float*)d_in[6];
    const float* bk = (const float*)d_in[7];
    const float* Wv = (const float*)d_in[8];
    const float* bv = (const float*)d_in[9];
    float* out = (float*)d_out;

    proj_kernel<<<dim3(NB * SEQ / 128, 3), 256>>>(Xq, Xk, Xv, Wq, bq, Wk, bk, Wv, bv);
    attn_kernel<<<256, 128>>>(out);
}

// round 6
// speedup vs baseline: 5.5733x; 1.0372x over previous
#include <cuda_runtime.h>
#include <cuda_bf16.h>
#include <cstdint>

#define SEQ 2048
#define NB 8
#define DM 512
#define DK 64
#define SCALE 0.125f   // 1/sqrt(64)

// bf16 hi/lo split Q,K,V; 2 bf16 packed per uint32 (low = even col)
__device__ uint32_t g_Qh[NB * SEQ * DK / 2], g_Ql[NB * SEQ * DK / 2];
__device__ uint32_t g_Kh[NB * SEQ * DK / 2], g_Kl[NB * SEQ * DK / 2];
__device__ uint32_t g_Vh[NB * SEQ * DK / 2], g_Vl[NB * SEQ * DK / 2];

#define SW128(x) ((x) ^ (((x) >> 3) & 0x70))

__device__ __forceinline__ uint32_t smem_u32(const void* p) {
    uint32_t a;
    asm("{ .reg .u64 t; cvta.to.shared.u64 t, %1; cvt.u32.u64 %0, t; }" : "=r"(a) : "l"(p));
    return a;
}

__device__ __forceinline__ void split2(float a, float b, uint32_t& h, uint32_t& l) {
    float ah = __bfloat162float(__float2bfloat16(a));
    float bh = __bfloat162float(__float2bfloat16(b));
    __nv_bfloat162 H = __floats2bfloat162_rn(a, b);        // low = a
    __nv_bfloat162 L = __floats2bfloat162_rn(a - ah, b - bh);
    h = *(uint32_t*)&H;
    l = *(uint32_t*)&L;
}

#define LDSM4(r0, r1, r2, r3, a) \
    asm volatile("ldmatrix.sync.aligned.m8n8.x4.shared.b16 {%0,%1,%2,%3}, [%4];" \
                 : "=r"(r0), "=r"(r1), "=r"(r2), "=r"(r3) : "r"(a))
#define LDSM4T(r0, r1, r2, r3, a) \
    asm volatile("ldmatrix.sync.aligned.m8n8.x4.trans.shared.b16 {%0,%1,%2,%3}, [%4];" \
                 : "=r"(r0), "=r"(r1), "=r"(r2), "=r"(r3) : "r"(a))
#define MMA(c, a, b0, b1) \
    asm volatile("mma.sync.aligned.m16n8k16.row.col.f32.bf16.bf16.f32 " \
                 "{%0,%1,%2,%3},{%4,%5,%6,%7},{%8,%9},{%0,%1,%2,%3};" \
                 : "+f"((c)[0]), "+f"((c)[1]), "+f"((c)[2]), "+f"((c)[3]) \
                 : "r"((a)[0]), "r"((a)[1]), "r"((a)[2]), "r"((a)[3]), "r"(b0), "r"(b1))

#define CP16(dst, src) \
    asm volatile("cp.async.cg.shared.global [%0], [%1], 16;" :: "r"(dst), "l"(src))
#define CP_COMMIT() asm volatile("cp.async.commit_group;" ::: "memory")
#define CP_WAIT(n)  asm volatile("cp.async.wait_group %0;" :: "n"(n) : "memory")

// ---------------------------------------------------------------------------
// Projection GEMM via mma.sync bf16 hi/lo with register-level prefetch:
// chunk c+1's LDGs are issued before chunk c's MMAs -> DRAM latency hidden.
// ---------------------------------------------------------------------------
__global__ __launch_bounds__(256) void proj_kernel(
    const float* __restrict__ Xq, const float* __restrict__ Xk, const float* __restrict__ Xv,
    const float* __restrict__ Wq, const float* __restrict__ bq,
    const float* __restrict__ Wk, const float* __restrict__ bk,
    const float* __restrict__ Wv, const float* __restrict__ bv)
{
    __shared__ __align__(128) unsigned char sm[49152];
    // XH @0 (16KB), XL @16384, WH @32768 (8KB), WL @40960

    const float* X; const float* W; const float* bias;
    uint32_t* Yh; uint32_t* Yl; float osc;
    const int which = blockIdx.y;
    if (which == 0)      { X = Xq; W = Wq; bias = bq; Yh = g_Qh; Yl = g_Ql; osc = SCALE; }
    else if (which == 1) { X = Xk; W = Wk; bias = bk; Yh = g_Kh; Yl = g_Kl; osc = 1.f; }
    else                 { X = Xv; W = Wv; bias = bv; Yh = g_Vh; Yl = g_Vl; osc = 1.f; }

    const int tid = threadIdx.x, lane = tid & 31, wid = tid >> 5;
    const int m0 = blockIdx.x * 128, mw = wid * 16;
    const uint32_t sb = smem_u32(sm);
    const int r8 = lane & 7, sub = lane >> 3;

    const int xrow = tid >> 1, xhalf = tid & 1;
    const int wrow = tid >> 2, wq4 = tid & 3;

    float acc[8][4];
    #pragma unroll
    for (int n = 0; n < 8; n++)
        #pragma unroll
        for (int e = 0; e < 4; e++) acc[n][e] = 0.f;

    // prefetch chunk 0 into registers
    float4 xr[8], wr[4];
    {
        const float4* xs = (const float4*)(X + (size_t)(m0 + xrow) * DM + xhalf * 32);
        #pragma unroll
        for (int i = 0; i < 8; i++) xr[i] = xs[i];
        const float4* ws = (const float4*)(W + (size_t)wrow * 64 + wq4 * 16);
        #pragma unroll
        for (int i = 0; i < 4; i++) wr[i] = ws[i];
    }

    for (int c = 0; c < 8; c++) {
        // split regs -> SMEM (swizzled)
        #pragma unroll
        for (int g4 = 0; g4 < 4; g4++) {
            float4 f0 = xr[g4 * 2], f1 = xr[g4 * 2 + 1];
            uint4 h, l;
            split2(f0.x, f0.y, h.x, l.x); split2(f0.z, f0.w, h.y, l.y);
            split2(f1.x, f1.y, h.z, l.z); split2(f1.z, f1.w, h.w, l.w);
            const uint32_t off = SW128(xrow * 128 + xhalf * 64 + g4 * 16);
            *(uint4*)(sm + off)         = h;
            *(uint4*)(sm + 16384 + off) = l;
        }
        #pragma unroll
        for (int g4 = 0; g4 < 2; g4++) {
            float4 f0 = wr[g4 * 2], f1 = wr[g4 * 2 + 1];
            uint4 h, l;
            split2(f0.x, f0.y, h.x, l.x); split2(f0.z, f0.w, h.y, l.y);
            split2(f1.x, f1.y, h.z, l.z); split2(f1.z, f1.w, h.w, l.w);
            const uint32_t off = SW128(wrow * 128 + wq4 * 32 + g4 * 16);
            *(uint4*)(sm + 32768 + off) = h;
            *(uint4*)(sm + 40960 + off) = l;
        }
        __syncthreads();

        // issue next chunk's LDGs now (latency overlaps the MMAs below)
        if (c < 7) {
            const int cn = c + 1;
            const float4* xs = (const float4*)(X + (size_t)(m0 + xrow) * DM + cn * 64 + xhalf * 32);
            #pragma unroll
            for (int i = 0; i < 8; i++) xr[i] = xs[i];
            const float4* ws = (const float4*)(W + (size_t)(cn * 64 + wrow) * 64 + wq4 * 16);
            #pragma unroll
            for (int i = 0; i < 4; i++) wr[i] = ws[i];
        }

        // A fragments (hi/lo) + B via ldmatrix.trans + MMAs
        uint32_t ah[4][4], al[4][4];
        #pragma unroll
        for (int kk = 0; kk < 4; kk++) {
            const int row = mw + r8 + ((sub & 1) << 3);
            const int byt = kk * 32 + ((sub >> 1) << 4);
            const uint32_t off = SW128(row * 128 + byt);
            LDSM4(ah[kk][0], ah[kk][1], ah[kk][2], ah[kk][3], sb + off);
            LDSM4(al[kk][0], al[kk][1], al[kk][2], al[kk][3], sb + 16384 + off);
        }
        #pragma unroll
        for (int j = 0; j < 4; j++) {
            #pragma unroll
            for (int kk = 0; kk < 4; kk++) {
                const int row = kk * 16 + r8 + ((sub & 1) << 3);
                const int byt = j * 32 + ((sub >> 1) << 4);
                const uint32_t off = SW128(row * 128 + byt);
                uint32_t h0, h1, h2, h3, u0, u1, u2, u3;
                LDSM4T(h0, h1, h2, h3, sb + 32768 + off);
                LDSM4T(u0, u1, u2, u3, sb + 40960 + off);
                MMA(acc[2 * j],     ah[kk], h0, h1);
                MMA(acc[2 * j],     al[kk], h0, h1);
                MMA(acc[2 * j],     ah[kk], u0, u1);
                MMA(acc[2 * j + 1], ah[kk], h2, h3);
                MMA(acc[2 * j + 1], al[kk], h2, h3);
                MMA(acc[2 * j + 1], ah[kk], u2, u3);
            }
        }
        __syncthreads();
    }

    const int g = lane >> 2, cb = (lane & 3) * 2;
    #pragma unroll
    for (int n = 0; n < 8; n++) {
        const int col = n * 8 + cb;
        const float b0 = bias[col], b1 = bias[col + 1];
        const size_t r0 = (size_t)(m0 + mw + g), r1 = r0 + 8;
        uint32_t h, l;
        split2((acc[n][0] + b0) * osc, (acc[n][1] + b1) * osc, h, l);
        Yh[r0 * 32 + (col >> 1)] = h;  Yl[r0 * 32 + (col >> 1)] = l;
        split2((acc[n][2] + b0) * osc, (acc[n][3] + b1) * osc, h, l);
        Yh[r1 * 32 + (col >> 1)] = h;  Yl[r1 * 32 + (col >> 1)] = l;
    }
}

// ---------------------------------------------------------------------------
// Causal flash attention: mma.sync bf16 hi/lo + cp.async double buffering.
// 128 threads / 4 warps; BM=64 q-rows (16/warp), BN=64 kv per tile.
// SMEM (dynamic 64KB): buf[2] x {KH,KL,VH,VL} each 8KB, SW128.
// Q staged once in buf1 region; fragments kept in registers.
// ---------------------------------------------------------------------------
__global__ __launch_bounds__(128) void attn_kernel(float* __restrict__ out)
{
    extern __shared__ __align__(128) unsigned char sm[];
    const uint32_t sb = smem_u32(sm);

    const int tid = threadIdx.x, lane = tid & 31, wid = tid >> 5;
    const int r8 = lane & 7, sub = lane >> 3;

    // balanced causal schedule (bids b and b+148 tend to share an SM)
    const int bid = blockIdx.x;
    int rank;
    if (bid < 108)      rank = 40 + bid;
    else if (bid < 148) rank = bid - 108;
    else                rank = 255 - (bid - 148);
    const int strip = 31 - (rank >> 3);
    const int b     = rank & 7;
    const int q0    = strip * 64;
    const int base  = b * SEQ;

    const int row = tid >> 1, half = tid & 1;
    const uint32_t soff = SW128(row * 128 + half * 64);   // this thread's swizzle base pattern
    // per-thread gmem element offset (uint32 units) for tile row
    const size_t gtoff = (size_t)row * 32 + half * 16;

    // ---- Q tile -> buf1 region (offsets 32768/40960), then fragments ----
    {
        const uint4* sh = (const uint4*)(g_Qh + (size_t)(base + q0) * 32 + gtoff);
        const uint4* sl = (const uint4*)(g_Ql + (size_t)(base + q0) * 32 + gtoff);
        #pragma unroll
        for (int g4 = 0; g4 < 4; g4++) {
            const uint32_t off = SW128(row * 128 + half * 64 + g4 * 16);
            *(uint4*)(sm + 32768 + off) = sh[g4];
            *(uint4*)(sm + 40960 + off) = sl[g4];
        }
    }
    __syncthreads();
    uint32_t qh[4][4], ql[4][4];
    #pragma unroll
    for (int kk = 0; kk < 4; kk++) {
        const int qr = wid * 16 + r8 + ((sub & 1) << 3);
        const int byt = kk * 32 + ((sub >> 1) << 4);
        const uint32_t off = SW128(qr * 128 + byt);
        LDSM4(qh[kk][0], qh[kk][1], qh[kk][2], qh[kk][3], sb + 32768 + off);
        LDSM4(ql[kk][0], ql[kk][1], ql[kk][2], ql[kk][3], sb + 40960 + off);
    }

    const int ntiles = strip + 1;

    // prefetch helper: tile t -> buffer (t&1)
    auto prefetch = [&](int t) {
        const int k0 = t * 64;
        const uint32_t bufb = sb + (uint32_t)(t & 1) * 32768;
        const size_t ge = (size_t)(base + k0) * 32 + gtoff;
        const uint32_t* kh = g_Kh + ge;
        const uint32_t* kl = g_Kl + ge;
        const uint32_t* vh = g_Vh + ge;
        const uint32_t* vl = g_Vl + ge;
        #pragma unroll
        for (int g4 = 0; g4 < 4; g4++) {
            const uint32_t off = SW128(row * 128 + half * 64 + g4 * 16);
            CP16(bufb + off,         kh + g4 * 4);
            CP16(bufb + 8192 + off,  kl + g4 * 4);
            CP16(bufb + 16384 + off, vh + g4 * 4);
            CP16(bufb + 24576 + off, vl + g4 * 4);
        }
        CP_COMMIT();
    };

    prefetch(0);
    __syncthreads();             // all warps done with Q region (buf1)
    if (ntiles > 1) prefetch(1);

    float od[8][4];
    #pragma unroll
    for (int n = 0; n < 8; n++)
        #pragma unroll
        for (int e = 0; e < 4; e++) od[n][e] = 0.f;
    float m0v = -1e30f, m1v = -1e30f, l0 = 0.f, l1 = 0.f;

    for (int t = 0; t < ntiles; t++) {
        if (t + 1 < ntiles) { CP_WAIT(1); } else { CP_WAIT(0); }
        __syncthreads();
        const uint32_t bufb = sb + (uint32_t)(t & 1) * 32768;

        // ---- GEMM1: S = Qh*Kh + Ql*Kh + Qh*Kl ----
        float sc[8][4];
        #pragma unroll
        for (int n = 0; n < 8; n++)
            #pragma unroll
            for (int e = 0; e < 4; e++) sc[n][e] = 0.f;

        #pragma unroll
        for (int j = 0; j < 4; j++) {
            #pragma unroll
            for (int kk = 0; kk < 4; kk++) {
                const int kr = j * 16 + r8 + ((sub & 2) << 2);
                const int byt = kk * 32 + ((sub & 1) << 4);
                const uint32_t off = SW128(kr * 128 + byt);
                uint32_t h0, h1, h2, h3, u0, u1, u2, u3;
                LDSM4(h0, h1, h2, h3, bufb + off);
                LDSM4(u0, u1, u2, u3, bufb + 8192 + off);
                MMA(sc[2 * j],     qh[kk], h0, h1);
                MMA(sc[2 * j],     ql[kk], h0, h1);
                MMA(sc[2 * j],     qh[kk], u0, u1);
                MMA(sc[2 * j + 1], qh[kk], h2, h3);
                MMA(sc[2 * j + 1], ql[kk], h2, h3);
                MMA(sc[2 * j + 1], qh[kk], u2, u3);
            }
        }

        // ---- mask (diagonal tile only) ----
        if (t == ntiles - 1) {
            const int cb = (lane & 3) * 2, rl = wid * 16 + (lane >> 2);
            #pragma unroll
            for (int n = 0; n < 8; n++) {
                const int c0 = n * 8 + cb;
                if (c0     > rl)     sc[n][0] = -1e30f;
                if (c0 + 1 > rl)     sc[n][1] = -1e30f;
                if (c0     > rl + 8) sc[n][2] = -1e30f;
                if (c0 + 1 > rl + 8) sc[n][3] = -1e30f;
            }
        }

        // ---- online softmax ----
        float rm0 = -1e30f, rm1 = -1e30f;
        #pragma unroll
        for (int n = 0; n < 8; n++) {
            rm0 = fmaxf(rm0, fmaxf(sc[n][0], sc[n][1]));
            rm1 = fmaxf(rm1, fmaxf(sc[n][2], sc[n][3]));
        }
        rm0 = fmaxf(rm0, __shfl_xor_sync(0xffffffffu, rm0, 1));
        rm0 = fmaxf(rm0, __shfl_xor_sync(0xffffffffu, rm0, 2));
        rm1 = fmaxf(rm1, __shfl_xor_sync(0xffffffffu, rm1, 1));
        rm1 = fmaxf(rm1, __shfl_xor_sync(0xffffffffu, rm1, 2));
        const float nm0 = fmaxf(m0v, rm0), nm1 = fmaxf(m1v, rm1);
        const float cor0 = __expf(m0v - nm0), cor1 = __expf(m1v - nm1);
        m0v = nm0; m1v = nm1;

        float rs0 = 0.f, rs1 = 0.f;
        #pragma unroll
        for (int n = 0; n < 8; n++) {
            sc[n][0] = __expf(sc[n][0] - nm0); rs0 += sc[n][0];
            sc[n][1] = __expf(sc[n][1] - nm0); rs0 += sc[n][1];
            sc[n][2] = __expf(sc[n][2] - nm1); rs1 += sc[n][2];
            sc[n][3] = __expf(sc[n][3] - nm1); rs1 += sc[n][3];
        }
        rs0 += __shfl_xor_sync(0xffffffffu, rs0, 1);
        rs0 += __shfl_xor_sync(0xffffffffu, rs0, 2);
        rs1 += __shfl_xor_sync(0xffffffffu, rs1, 1);
        rs1 += __shfl_xor_sync(0xffffffffu, rs1, 2);
        l0 = l0 * cor0 + rs0;
        l1 = l1 * cor1 + rs1;
        #pragma unroll
        for (int n = 0; n < 8; n++) {
            od[n][0] *= cor0; od[n][1] *= cor0;
            od[n][2] *= cor1; od[n][3] *= cor1;
        }

        // ---- pack P accumulators as A-fragments ----
        uint32_t ph[4][4], pl[4][4];
        #pragma unroll
        for (int kk = 0; kk < 4; kk++) {
            split2(sc[2 * kk][0],     sc[2 * kk][1],     ph[kk][0], pl[kk][0]);
            split2(sc[2 * kk][2],     sc[2 * kk][3],     ph[kk][1], pl[kk][1]);
            split2(sc[2 * kk + 1][0], sc[2 * kk + 1][1], ph[kk][2], pl[kk][2]);
            split2(sc[2 * kk + 1][2], sc[2 * kk + 1][3], ph[kk][3], pl[kk][3]);
        }

        // ---- GEMM2: O += Ph*Vh + Pl*Vh + Ph*Vl ----
        #pragma unroll
        for (int j = 0; j < 4; j++) {
            #pragma unroll
            for (int kk = 0; kk < 4; kk++) {
                const int vr = kk * 16 + r8 + ((sub & 1) << 3);
                const int byt = j * 32 + ((sub >> 1) << 4);
                const uint32_t off = SW128(vr * 128 + byt);
                uint32_t h0, h1, h2, h3, u0, u1, u2, u3;
                LDSM4T(h0, h1, h2, h3, bufb + 16384 + off);
                LDSM4T(u0, u1, u2, u3, bufb + 24576 + off);
                MMA(od[2 * j],     ph[kk], h0, h1);
                MMA(od[2 * j],     pl[kk], h0, h1);
                MMA(od[2 * j],     ph[kk], u0, u1);
                MMA(od[2 * j + 1], ph[kk], h2, h3);
                MMA(od[2 * j + 1], pl[kk], h2, h3);
                MMA(od[2 * j + 1], ph[kk], u2, u3);
            }
        }
        __syncthreads();                 // all warps done reading buf[t&1]
        if (t + 2 < ntiles) prefetch(t + 2);
    }

    // ---- epilogue ----
    const float inv0 = 1.f / l0, inv1 = 1.f / l1;
    const int g = lane >> 2, cb = (lane & 3) * 2;
    const size_t r0 = (size_t)b * SEQ + q0 + wid * 16 + g, r1 = r0 + 8;
    #pragma unroll
    for (int n = 0; n < 8; n++) {
        float2 o0 = make_float2(od[n][0] * inv0, od[n][1] * inv0);
        float2 o1 = make_float2(od[n][2] * inv1, od[n][3] * inv1);
        *(float2*)(out + r0 * DK + n * 8 + cb) = o0;
        *(float2*)(out + r1 * DK + n * 8 + cb) = o1;
    }
}

// ---------------------------------------------------------------------------
extern "C" void kernel_launch(void* const* d_in, const int* in_sizes, int n_in,
                              void* d_out, int out_size)
{
    (void)in_sizes; (void)n_in; (void)out_size;
    const float* Xq = (const float*)d_in[0];
    const float* Xk = (const float*)d_in[1];
    const float* Xv = (const float*)d_in[2];
    // d_in[3] = mask (analytically causal; not read)
    const float* Wq = (const float*)d_in[4];
    const float* bq = (const float*)d_in[5];
    const float* Wk = (const float*)d_in[6];
    const float* bk = (const float*)d_in[7];
    const float* Wv = (const float*)d_in[8];
    const float* bv = (const float*)d_in[9];
    float* out = (float*)d_out;

    static bool attr_set = false;
    if (!attr_set) {
        cudaFuncSetAttribute(attn_kernel, cudaFuncAttributeMaxDynamicSharedMemorySize, 65536);
        attr_set = true;
    }

    proj_kernel<<<dim3(NB * SEQ / 128, 3), 256>>>(Xq, Xk, Xv, Wq, bq, Wk, bk, Wv, bv);
    attn_kernel<<<256, 128, 65536>>>(out);
}

// round 8
// speedup vs baseline: 6.6312x; 1.1898x over previous
#include <cuda_runtime.h>
#include <cuda_bf16.h>
#include <cstdint>

#define SEQ 2048
#define NB 8
#define DM 512
#define DK 64
#define SCALE 0.125f           // 1/sqrt(64)
#define LOG2E 1.4426950408889634f

// bf16 hi/lo split Q,K,V; 2 bf16 packed per uint32 (low = even col)
__device__ uint32_t g_Qh[NB * SEQ * DK / 2], g_Ql[NB * SEQ * DK / 2];
__device__ uint32_t g_Kh[NB * SEQ * DK / 2], g_Kl[NB * SEQ * DK / 2];
__device__ uint32_t g_Vh[NB * SEQ * DK / 2], g_Vl[NB * SEQ * DK / 2];

// Pre-packed, pre-swizzled W hi/lo SMEM images: [which][chunk][8192 bytes]
// per-matrix stride = 8 chunks * 8192 B = 65536 B  (R7 bug: used 32768)
__device__ uint4 g_Wph[3 * 8 * 512], g_Wpl[3 * 8 * 512];

// kv-split partials: [seg 0..2][b][row][dim], and (m,l) pairs
__device__ float g_Op[3 * NB * SEQ * DK];
__device__ float g_Ml[3 * NB * SEQ * 2];

#define SW128(x) ((x) ^ (((x) >> 3) & 0x70))

__device__ __forceinline__ uint32_t smem_u32(const void* p) {
    uint32_t a;
    asm("{ .reg .u64 t; cvta.to.shared.u64 t, %1; cvt.u32.u64 %0, t; }" : "=r"(a) : "l"(p));
    return a;
}

__device__ __forceinline__ void split2(float a, float b, uint32_t& h, uint32_t& l) {
    float ah = __bfloat162float(__float2bfloat16(a));
    float bh = __bfloat162float(__float2bfloat16(b));
    __nv_bfloat162 H = __floats2bfloat162_rn(a, b);        // low = a
    __nv_bfloat162 L = __floats2bfloat162_rn(a - ah, b - bh);
    h = *(uint32_t*)&H;
    l = *(uint32_t*)&L;
}

__device__ __forceinline__ float ex2(float x) {
    float r;
    asm("ex2.approx.f32 %0, %1;" : "=f"(r) : "f"(x));
    return r;
}

#define LDSM4(r0, r1, r2, r3, a) \
    asm volatile("ldmatrix.sync.aligned.m8n8.x4.shared.b16 {%0,%1,%2,%3}, [%4];" \
                 : "=r"(r0), "=r"(r1), "=r"(r2), "=r"(r3) : "r"(a))
#define LDSM4T(r0, r1, r2, r3, a) \
    asm volatile("ldmatrix.sync.aligned.m8n8.x4.trans.shared.b16 {%0,%1,%2,%3}, [%4];" \
                 : "=r"(r0), "=r"(r1), "=r"(r2), "=r"(r3) : "r"(a))
#define MMA(c, a, b0, b1) \
    asm volatile("mma.sync.aligned.m16n8k16.row.col.f32.bf16.bf16.f32 " \
                 "{%0,%1,%2,%3},{%4,%5,%6,%7},{%8,%9},{%0,%1,%2,%3};" \
                 : "+f"((c)[0]), "+f"((c)[1]), "+f"((c)[2]), "+f"((c)[3]) \
                 : "r"((a)[0]), "r"((a)[1]), "r"((a)[2]), "r"((a)[3]), "r"(b0), "r"(b1))

#define CP16(dst, src) \
    asm volatile("cp.async.cg.shared.global [%0], [%1], 16;" :: "r"(dst), "l"(src))
#define CP_COMMIT() asm volatile("cp.async.commit_group;" ::: "memory")
#define CP_WAIT(n)  asm volatile("cp.async.wait_group %0;" :: "n"(n) : "memory")

// ---------------------------------------------------------------------------
// W prep: convert 3 weight matrices to hi/lo bf16, pre-swizzled SMEM images.
// ---------------------------------------------------------------------------
__global__ __launch_bounds__(256) void wprep_kernel(
    const float* __restrict__ Wq, const float* __restrict__ Wk, const float* __restrict__ Wv)
{
    const int which = blockIdx.x;
    const float* W = (which == 0) ? Wq : (which == 1) ? Wk : Wv;
    const int tid = threadIdx.x;
    const int wrow = tid >> 2, wq4 = tid & 3;
    unsigned char* dh = (unsigned char*)g_Wph + which * 65536;
    unsigned char* dl = (unsigned char*)g_Wpl + which * 65536;

    for (int c = 0; c < 8; c++) {
        const float4* src = (const float4*)(W + (size_t)(c * 64 + wrow) * 64 + wq4 * 16);
        #pragma unroll
        for (int g4 = 0; g4 < 2; g4++) {
            float4 f0 = src[g4 * 2], f1 = src[g4 * 2 + 1];
            uint4 h, l;
            split2(f0.x, f0.y, h.x, l.x); split2(f0.z, f0.w, h.y, l.y);
            split2(f1.x, f1.y, h.z, l.z); split2(f1.z, f1.w, h.w, l.w);
            const uint32_t off = SW128(wrow * 128 + wq4 * 32 + g4 * 16);
            *(uint4*)(dh + c * 8192 + off) = h;
            *(uint4*)(dl + c * 8192 + off) = l;
        }
    }
}

// ---------------------------------------------------------------------------
// Projection GEMM via mma.sync bf16 hi/lo; X converted in-kernel (register
// prefetch), W copied raw from precomputed swizzled images.
// Q outputs pre-scaled by SCALE*LOG2E (exp2-domain softmax downstream).
// ---------------------------------------------------------------------------
__global__ __launch_bounds__(256) void proj_kernel(
    const float* __restrict__ Xq, const float* __restrict__ Xk, const float* __restrict__ Xv,
    const float* __restrict__ bq, const float* __restrict__ bk, const float* __restrict__ bv)
{
    __shared__ __align__(128) unsigned char sm[49152];
    // XH @0 (16KB), XL @16384, WH @32768 (8KB), WL @40960

    const float* X; const float* bias;
    uint32_t* Yh; uint32_t* Yl; float osc;
    const int which = blockIdx.y;
    if (which == 0)      { X = Xq; bias = bq; Yh = g_Qh; Yl = g_Ql; osc = SCALE * LOG2E; }
    else if (which == 1) { X = Xk; bias = bk; Yh = g_Kh; Yl = g_Kl; osc = 1.f; }
    else                 { X = Xv; bias = bv; Yh = g_Vh; Yl = g_Vl; osc = 1.f; }

    const unsigned char* wph = (const unsigned char*)g_Wph + which * 65536;
    const unsigned char* wpl = (const unsigned char*)g_Wpl + which * 65536;

    const int tid = threadIdx.x, lane = tid & 31, wid = tid >> 5;
    const int m0 = blockIdx.x * 128, mw = wid * 16;
    const uint32_t sb = smem_u32(sm);
    const int r8 = lane & 7, sub = lane >> 3;
    const int xrow = tid >> 1, xhalf = tid & 1;

    float acc[8][4];
    #pragma unroll
    for (int n = 0; n < 8; n++)
        #pragma unroll
        for (int e = 0; e < 4; e++) acc[n][e] = 0.f;

    // prefetch chunk 0
    float4 xr[8];
    uint4 wh[2], wl[2];
    {
        const float4* xs = (const float4*)(X + (size_t)(m0 + xrow) * DM + xhalf * 32);
        #pragma unroll
        for (int i = 0; i < 8; i++) xr[i] = xs[i];
        #pragma unroll
        for (int i = 0; i < 2; i++) {
            wh[i] = *(const uint4*)(wph + tid * 32 + i * 16);
            wl[i] = *(const uint4*)(wpl + tid * 32 + i * 16);
        }
    }

    for (int c = 0; c < 8; c++) {
        // X regs -> split -> SMEM (swizzled); W regs raw copy
        #pragma unroll
        for (int g4 = 0; g4 < 4; g4++) {
            float4 f0 = xr[g4 * 2], f1 = xr[g4 * 2 + 1];
            uint4 h, l;
            split2(f0.x, f0.y, h.x, l.x); split2(f0.z, f0.w, h.y, l.y);
            split2(f1.x, f1.y, h.z, l.z); split2(f1.z, f1.w, h.w, l.w);
            const uint32_t off = SW128(xrow * 128 + xhalf * 64 + g4 * 16);
            *(uint4*)(sm + off)         = h;
            *(uint4*)(sm + 16384 + off) = l;
        }
        #pragma unroll
        for (int i = 0; i < 2; i++) {
            *(uint4*)(sm + 32768 + tid * 32 + i * 16) = wh[i];
            *(uint4*)(sm + 40960 + tid * 32 + i * 16) = wl[i];
        }
        __syncthreads();

        // prefetch next chunk (latency overlaps MMAs below)
        if (c < 7) {
            const int cn = c + 1;
            const float4* xs = (const float4*)(X + (size_t)(m0 + xrow) * DM + cn * 64 + xhalf * 32);
            #pragma unroll
            for (int i = 0; i < 8; i++) xr[i] = xs[i];
            #pragma unroll
            for (int i = 0; i < 2; i++) {
                wh[i] = *(const uint4*)(wph + cn * 8192 + tid * 32 + i * 16);
                wl[i] = *(const uint4*)(wpl + cn * 8192 + tid * 32 + i * 16);
            }
        }

        uint32_t ah[4][4], al[4][4];
        #pragma unroll
        for (int kk = 0; kk < 4; kk++) {
            const int row = mw + r8 + ((sub & 1) << 3);
            const int byt = kk * 32 + ((sub >> 1) << 4);
            const uint32_t off = SW128(row * 128 + byt);
            LDSM4(ah[kk][0], ah[kk][1], ah[kk][2], ah[kk][3], sb + off);
            LDSM4(al[kk][0], al[kk][1], al[kk][2], al[kk][3], sb + 16384 + off);
        }
        #pragma unroll
        for (int j = 0; j < 4; j++) {
            #pragma unroll
            for (int kk = 0; kk < 4; kk++) {
                const int row = kk * 16 + r8 + ((sub & 1) << 3);
                const int byt = j * 32 + ((sub >> 1) << 4);
                const uint32_t off = SW128(row * 128 + byt);
                uint32_t h0, h1, h2, h3, u0, u1, u2, u3;
                LDSM4T(h0, h1, h2, h3, sb + 32768 + off);
                LDSM4T(u0, u1, u2, u3, sb + 40960 + off);
                MMA(acc[2 * j],     ah[kk], h0, h1);
                MMA(acc[2 * j],     al[kk], h0, h1);
                MMA(acc[2 * j],     ah[kk], u0, u1);
                MMA(acc[2 * j + 1], ah[kk], h2, h3);
                MMA(acc[2 * j + 1], al[kk], h2, h3);
                MMA(acc[2 * j + 1], ah[kk], u2, u3);
            }
        }
        __syncthreads();
    }

    const int g = lane >> 2, cb = (lane & 3) * 2;
    #pragma unroll
    for (int n = 0; n < 8; n++) {
        const int col = n * 8 + cb;
        const float b0 = bias[col], b1 = bias[col + 1];
        const size_t r0 = (size_t)(m0 + mw + g), r1 = r0 + 8;
        uint32_t h, l;
        split2((acc[n][0] + b0) * osc, (acc[n][1] + b1) * osc, h, l);
        Yh[r0 * 32 + (col >> 1)] = h;  Yl[r0 * 32 + (col >> 1)] = l;
        split2((acc[n][2] + b0) * osc, (acc[n][3] + b1) * osc, h, l);
        Yh[r1 * 32 + (col >> 1)] = h;  Yl[r1 * 32 + (col >> 1)] = l;
    }
}

// ---------------------------------------------------------------------------
// Segmented causal flash attention (kv-split), mma.sync bf16 hi/lo, cp.async
// double buffering. 504 CTAs: strip s has ceil((s+1)/11) segments of <=11
// kv tiles. Single-seg strips write out directly; multi-seg write partials.
// ---------------------------------------------------------------------------
__global__ void __launch_bounds__(128, 3) attn_kernel(float* __restrict__ out)
{
    extern __shared__ __align__(128) unsigned char sm[];
    const uint32_t sb = smem_u32(sm);

    const int tid = threadIdx.x, lane = tid & 31, wid = tid >> 5;
    const int r8 = lane & 7, sub = lane >> 3;

    // ---- work mapping: longest segments first ----
    const int u = blockIdx.x >> 3, b = blockIdx.x & 7;
    int s, seg;
    if (u < 30)      { s = 31 - u / 3;          seg = u % 3; }
    else if (u < 52) { int v = u - 30; s = 21 - (v >> 1); seg = v & 1; }
    else             { s = 10 - (u - 52);       seg = 0; }
    const int n     = s + 1;
    const int nseg  = (s + 11) / 11;
    const int bse   = n / nseg, rem = n % nseg;
    const int len   = bse + (seg < rem ? 1 : 0);
    const int t0    = seg * bse + (seg < rem ? seg : rem);
    const bool diag = (seg == nseg - 1);

    const int q0   = s * 64;
    const int base = b * SEQ;

    const int row = tid >> 1, half = tid & 1;
    const size_t gtoff = (size_t)row * 32 + half * 16;

    // ---- Q tile -> buf1 region, then fragments ----
    {
        const uint4* sh = (const uint4*)(g_Qh + (size_t)(base + q0) * 32 + gtoff);
        const uint4* sl = (const uint4*)(g_Ql + (size_t)(base + q0) * 32 + gtoff);
        #pragma unroll
        for (int g4 = 0; g4 < 4; g4++) {
            const uint32_t off = SW128(row * 128 + half * 64 + g4 * 16);
            *(uint4*)(sm + 32768 + off) = sh[g4];
            *(uint4*)(sm + 40960 + off) = sl[g4];
        }
    }
    __syncthreads();
    uint32_t qh[4][4], ql[4][4];
    #pragma unroll
    for (int kk = 0; kk < 4; kk++) {
        const int qr = wid * 16 + r8 + ((sub & 1) << 3);
        const int byt = kk * 32 + ((sub >> 1) << 4);
        const uint32_t off = SW128(qr * 128 + byt);
        LDSM4(qh[kk][0], qh[kk][1], qh[kk][2], qh[kk][3], sb + 32768 + off);
        LDSM4(ql[kk][0], ql[kk][1], ql[kk][2], ql[kk][3], sb + 40960 + off);
    }

    auto prefetch = [&](int i) {
        const int k0 = (t0 + i) * 64;
        const uint32_t bufb = sb + (uint32_t)(i & 1) * 32768;
        const size_t ge = (size_t)(base + k0) * 32 + gtoff;
        #pragma unroll
        for (int g4 = 0; g4 < 4; g4++) {
            const uint32_t off = SW128(row * 128 + half * 64 + g4 * 16);
            CP16(bufb + off,         g_Kh + ge + g4 * 4);
            CP16(bufb + 8192 + off,  g_Kl + ge + g4 * 4);
            CP16(bufb + 16384 + off, g_Vh + ge + g4 * 4);
            CP16(bufb + 24576 + off, g_Vl + ge + g4 * 4);
        }
        CP_COMMIT();
    };

    prefetch(0);
    __syncthreads();             // all warps done reading Q region (buf1)
    if (len > 1) prefetch(1);

    float od[8][4];
    #pragma unroll
    for (int nn = 0; nn < 8; nn++)
        #pragma unroll
        for (int e = 0; e < 4; e++) od[nn][e] = 0.f;
    float m0v = -1e30f, m1v = -1e30f, l0 = 0.f, l1 = 0.f;

    for (int i = 0; i < len; i++) {
        if (i + 1 < len) { CP_WAIT(1); } else { CP_WAIT(0); }
        __syncthreads();
        const uint32_t bufb = sb + (uint32_t)(i & 1) * 32768;

        // ---- GEMM1: S = Qh*Kh + Ql*Kh + Qh*Kl (log2-domain, scale folded) --
        float sc[8][4];
        #pragma unroll
        for (int nn = 0; nn < 8; nn++)
            #pragma unroll
            for (int e = 0; e < 4; e++) sc[nn][e] = 0.f;

        #pragma unroll
        for (int j = 0; j < 4; j++) {
            #pragma unroll
            for (int kk = 0; kk < 4; kk++) {
                const int kr = j * 16 + r8 + ((sub & 2) << 2);
                const int byt = kk * 32 + ((sub & 1) << 4);
                const uint32_t off = SW128(kr * 128 + byt);
                uint32_t h0, h1, h2, h3, u0, u1, u2, u3;
                LDSM4(h0, h1, h2, h3, bufb + off);
                LDSM4(u0, u1, u2, u3, bufb + 8192 + off);
                MMA(sc[2 * j],     qh[kk], h0, h1);
                MMA(sc[2 * j],     ql[kk], h0, h1);
                MMA(sc[2 * j],     qh[kk], u0, u1);
                MMA(sc[2 * j + 1], qh[kk], h2, h3);
                MMA(sc[2 * j + 1], ql[kk], h2, h3);
                MMA(sc[2 * j + 1], qh[kk], u2, u3);
            }
        }

        // ---- mask (diagonal tile only) ----
        if (diag && i == len - 1) {
            const int cb = (lane & 3) * 2, rl = wid * 16 + (lane >> 2);
            #pragma unroll
            for (int nn = 0; nn < 8; nn++) {
                const int c0 = nn * 8 + cb;
                if (c0     > rl)     sc[nn][0] = -1e30f;
                if (c0 + 1 > rl)     sc[nn][1] = -1e30f;
                if (c0     > rl + 8) sc[nn][2] = -1e30f;
                if (c0 + 1 > rl + 8) sc[nn][3] = -1e30f;
            }
        }

        // ---- online softmax (exp2 domain) ----
        float rm0 = -1e30f, rm1 = -1e30f;
        #pragma unroll
        for (int nn = 0; nn < 8; nn++) {
            rm0 = fmaxf(rm0, fmaxf(sc[nn][0], sc[nn][1]));
            rm1 = fmaxf(rm1, fmaxf(sc[nn][2], sc[nn][3]));
        }
        rm0 = fmaxf(rm0, __shfl_xor_sync(0xffffffffu, rm0, 1));
        rm0 = fmaxf(rm0, __shfl_xor_sync(0xffffffffu, rm0, 2));
        rm1 = fmaxf(rm1, __shfl_xor_sync(0xffffffffu, rm1, 1));
        rm1 = fmaxf(rm1, __shfl_xor_sync(0xffffffffu, rm1, 2));
        const float nm0 = fmaxf(m0v, rm0), nm1 = fmaxf(m1v, rm1);
        const float cor0 = ex2(m0v - nm0), cor1 = ex2(m1v - nm1);
        m0v = nm0; m1v = nm1;

        float rs0 = 0.f, rs1 = 0.f;
        #pragma unroll
        for (int nn = 0; nn < 8; nn++) {
            sc[nn][0] = ex2(sc[nn][0] - nm0); rs0 += sc[nn][0];
            sc[nn][1] = ex2(sc[nn][1] - nm0); rs0 += sc[nn][1];
            sc[nn][2] = ex2(sc[nn][2] - nm1); rs1 += sc[nn][2];
            sc[nn][3] = ex2(sc[nn][3] - nm1); rs1 += sc[nn][3];
        }
        rs0 += __shfl_xor_sync(0xffffffffu, rs0, 1);
        rs0 += __shfl_xor_sync(0xffffffffu, rs0, 2);
        rs1 += __shfl_xor_sync(0xffffffffu, rs1, 1);
        rs1 += __shfl_xor_sync(0xffffffffu, rs1, 2);
        l0 = l0 * cor0 + rs0;
        l1 = l1 * cor1 + rs1;
        #pragma unroll
        for (int nn = 0; nn < 8; nn++) {
            od[nn][0] *= cor0; od[nn][1] *= cor0;
            od[nn][2] *= cor1; od[nn][3] *= cor1;
        }

        // ---- pack P accumulators as A-fragments ----
        uint32_t ph[4][4], pl[4][4];
        #pragma unroll
        for (int kk = 0; kk < 4; kk++) {
            split2(sc[2 * kk][0],     sc[2 * kk][1],     ph[kk][0], pl[kk][0]);
            split2(sc[2 * kk][2],     sc[2 * kk][3],     ph[kk][1], pl[kk][1]);
            split2(sc[2 * kk + 1][0], sc[2 * kk + 1][1], ph[kk][2], pl[kk][2]);
            split2(sc[2 * kk + 1][2], sc[2 * kk + 1][3], ph[kk][3], pl[kk][3]);
        }

        // ---- GEMM2: O += Ph*Vh + Pl*Vh + Ph*Vl ----
        #pragma unroll
        for (int j = 0; j < 4; j++) {
            #pragma unroll
            for (int kk = 0; kk < 4; kk++) {
                const int vr = kk * 16 + r8 + ((sub & 1) << 3);
                const int byt = j * 32 + ((sub >> 1) << 4);
                const uint32_t off = SW128(vr * 128 + byt);
                uint32_t h0, h1, h2, h3, u0, u1, u2, u3;
                LDSM4T(h0, h1, h2, h3, bufb + 16384 + off);
                LDSM4T(u0, u1, u2, u3, bufb + 24576 + off);
                MMA(od[2 * j],     ph[kk], h0, h1);
                MMA(od[2 * j],     pl[kk], h0, h1);
                MMA(od[2 * j],     ph[kk], u0, u1);
                MMA(od[2 * j + 1], ph[kk], h2, h3);
                MMA(od[2 * j + 1], pl[kk], h2, h3);
                MMA(od[2 * j + 1], ph[kk], u2, u3);
            }
        }
        __syncthreads();
        if (i + 2 < len) prefetch(i + 2);
    }

    // ---- epilogue ----
    const int g = lane >> 2, cb = (lane & 3) * 2;
    const int lr0 = wid * 16 + g;                 // local row in strip
    if (nseg == 1) {
        const float inv0 = 1.f / l0, inv1 = 1.f / l1;
        const size_t r0 = (size_t)base + q0 + lr0, r1 = r0 + 8;
        #pragma unroll
        for (int nn = 0; nn < 8; nn++) {
            *(float2*)(out + r0 * DK + nn * 8 + cb) = make_float2(od[nn][0] * inv0, od[nn][1] * inv0);
            *(float2*)(out + r1 * DK + nn * 8 + cb) = make_float2(od[nn][2] * inv1, od[nn][3] * inv1);
        }
    } else {
        const size_t pr0 = ((size_t)seg * NB + b) * SEQ + q0 + lr0, pr1 = pr0 + 8;
        #pragma unroll
        for (int nn = 0; nn < 8; nn++) {
            *(float2*)(g_Op + pr0 * DK + nn * 8 + cb) = make_float2(od[nn][0], od[nn][1]);
            *(float2*)(g_Op + pr1 * DK + nn * 8 + cb) = make_float2(od[nn][2], od[nn][3]);
        }
        if ((lane & 3) == 0) {
            g_Ml[pr0 * 2] = m0v;  g_Ml[pr0 * 2 + 1] = l0;
            g_Ml[pr1 * 2] = m1v;  g_Ml[pr1 * 2 + 1] = l1;
        }
    }
}

// ---------------------------------------------------------------------------
// Combine kv-split partials for rows in strips >= 11 (rows 704..2047 / batch).
// 4 threads per row, 16 dims each.
// ---------------------------------------------------------------------------
__global__ __launch_bounds__(128) void combine_kernel(float* __restrict__ out)
{
    const int idx = blockIdx.x * 128 + threadIdx.x;     // 8*1344*4 total
    const int q  = idx & 3;
    const int rb = idx >> 2;
    const int row = 704 + (rb % 1344);
    const int b   = rb / 1344;
    const int strip = row >> 6;
    const int nseg  = (strip + 11) / 11;                // 2 or 3

    float mg[3], lg[3];
    float M = -1e30f;
    for (int g = 0; g < nseg; g++) {
        const size_t pr = ((size_t)g * NB + b) * SEQ + row;
        mg[g] = g_Ml[pr * 2];
        lg[g] = g_Ml[pr * 2 + 1];
        M = fmaxf(M, mg[g]);
    }
    float l = 0.f;
    float4 o[4] = {{0,0,0,0},{0,0,0,0},{0,0,0,0},{0,0,0,0}};
    for (int g = 0; g < nseg; g++) {
        const float w = ex2(mg[g] - M);
        l += lg[g] * w;
        const float4* src = (const float4*)(g_Op + (((size_t)g * NB + b) * SEQ + row) * DK + q * 16);
        #pragma unroll
        for (int k = 0; k < 4; k++) {
            float4 v = src[k];
            o[k].x += w * v.x; o[k].y += w * v.y;
            o[k].z += w * v.z; o[k].w += w * v.w;
        }
    }
    const float inv = 1.f / l;
    float4* dst = (float4*)(out + ((size_t)b * SEQ + row) * DK + q * 16);
    #pragma unroll
    for (int k = 0; k < 4; k++) {
        o[k].x *= inv; o[k].y *= inv; o[k].z *= inv; o[k].w *= inv;
        dst[k] = o[k];
    }
}

// ---------------------------------------------------------------------------
extern "C" void kernel_launch(void* const* d_in, const int* in_sizes, int n_in,
                              void* d_out, int out_size)
{
    (void)in_sizes; (void)n_in; (void)out_size;
    const float* Xq = (const float*)d_in[0];
    const float* Xk = (const float*)d_in[1];
    const float* Xv = (const float*)d_in[2];
    // d_in[3] = mask (analytically causal; not read)
    const float* Wq = (const float*)d_in[4];
    const float* bq = (const float*)d_in[5];
    const float* Wk = (const float*)d_in[6];
    const float* bk = (const float*)d_in[7];
    const float* Wv = (const float*)d_in[8];
    const float* bv = (const float*)d_in[9];
    float* out = (float*)d_out;

    cudaFuncSetAttribute(attn_kernel, cudaFuncAttributeMaxDynamicSharedMemorySize, 65536);

    wprep_kernel<<<3, 256>>>(Wq, Wk, Wv);
    proj_kernel<<<dim3(NB * SEQ / 128, 3), 256>>>(Xq, Xk, Xv, bq, bk, bv);
    attn_kernel<<<504, 128, 65536>>>(out);
    combine_kernel<<<(NB * 1344 * 4) / 128, 128>>>(out);
}

// round 9
// speedup vs baseline: 7.3992x; 1.1158x over previous
#include <cuda_runtime.h>
#include <cuda_fp16.h>
#include <cstdint>

#define SEQ 2048
#define NB 8
#define DM 512
#define DK 64
#define CEXP 0.18033688011112042f   // (1/sqrt(64)) * log2(e)

// fp16 hi/lo split Q,K (2 fp16 per uint32, low = even col); V single fp16
__device__ uint32_t g_Qh[NB * SEQ * DK / 2], g_Ql[NB * SEQ * DK / 2];
__device__ uint32_t g_Kh[NB * SEQ * DK / 2], g_Kl[NB * SEQ * DK / 2];
__device__ uint32_t g_Vh[NB * SEQ * DK / 2];

// Pre-packed, pre-swizzled (16*W) hi/lo fp16 images: [which][chunk 8][8192 B]
__device__ uint4 g_Wph[3 * 8 * 512], g_Wpl[3 * 8 * 512];

// kv-split partials: [seg 0..2][b][row][dim], and (m,l) pairs
__device__ float g_Op[3 * NB * SEQ * DK];
__device__ float g_Ml[3 * NB * SEQ * 2];

#define SW128(x) ((x) ^ (((x) >> 3) & 0x70))

__device__ __forceinline__ uint32_t smem_u32(const void* p) {
    uint32_t a;
    asm("{ .reg .u64 t; cvta.to.shared.u64 t, %1; cvt.u32.u64 %0, t; }" : "=r"(a) : "l"(p));
    return a;
}

// fp16 hi/lo split of two floats
__device__ __forceinline__ void split2(float a, float b, uint32_t& h, uint32_t& l) {
    __half2 H = __floats2half2_rn(a, b);
    float ah = __half2float(__low2half(H));
    float bh = __half2float(__high2half(H));
    __half2 L = __floats2half2_rn(a - ah, b - bh);
    h = *(uint32_t*)&H;
    l = *(uint32_t*)&L;
}
__device__ __forceinline__ uint32_t pack2(float a, float b) {
    __half2 H = __floats2half2_rn(a, b);
    return *(uint32_t*)&H;
}

__device__ __forceinline__ float ex2(float x) {
    float r;
    asm("ex2.approx.f32 %0, %1;" : "=f"(r) : "f"(x));
    return r;
}

#define LDSM4(r0, r1, r2, r3, a) \
    asm volatile("ldmatrix.sync.aligned.m8n8.x4.shared.b16 {%0,%1,%2,%3}, [%4];" \
                 : "=r"(r0), "=r"(r1), "=r"(r2), "=r"(r3) : "r"(a))
#define LDSM4T(r0, r1, r2, r3, a) \
    asm volatile("ldmatrix.sync.aligned.m8n8.x4.trans.shared.b16 {%0,%1,%2,%3}, [%4];" \
                 : "=r"(r0), "=r"(r1), "=r"(r2), "=r"(r3) : "r"(a))
#define MMA(c, a, b0, b1) \
    asm volatile("mma.sync.aligned.m16n8k16.row.col.f32.f16.f16.f32 " \
                 "{%0,%1,%2,%3},{%4,%5,%6,%7},{%8,%9},{%0,%1,%2,%3};" \
                 : "+f"((c)[0]), "+f"((c)[1]), "+f"((c)[2]), "+f"((c)[3]) \
                 : "r"((a)[0]), "r"((a)[1]), "r"((a)[2]), "r"((a)[3]), "r"(b0), "r"(b1))

#define CP16(dst, src) \
    asm volatile("cp.async.cg.shared.global [%0], [%1], 16;" :: "r"(dst), "l"(src))
#define CP_COMMIT() asm volatile("cp.async.commit_group;" ::: "memory")
#define CP_WAIT(n)  asm volatile("cp.async.wait_group %0;" :: "n"(n) : "memory")

// ---------------------------------------------------------------------------
// W prep: 16*W -> fp16 hi/lo pre-swizzled images (x16 keeps residuals normal;
// proj epilogue multiplies by 1/16 — exact power-of-2, no extra rounding).
// ---------------------------------------------------------------------------
__global__ __launch_bounds__(256) void wprep_kernel(
    const float* __restrict__ Wq, const float* __restrict__ Wk, const float* __restrict__ Wv)
{
    const int which = blockIdx.x;
    const float* W = (which == 0) ? Wq : (which == 1) ? Wk : Wv;
    const int tid = threadIdx.x;
    const int wrow = tid >> 2, wq4 = tid & 3;
    unsigned char* dh = (unsigned char*)g_Wph + which * 65536;
    unsigned char* dl = (unsigned char*)g_Wpl + which * 65536;

    for (int c = 0; c < 8; c++) {
        const float4* src = (const float4*)(W + (size_t)(c * 64 + wrow) * 64 + wq4 * 16);
        #pragma unroll
        for (int g4 = 0; g4 < 2; g4++) {
            float4 f0 = src[g4 * 2], f1 = src[g4 * 2 + 1];
            uint4 h, l;
            split2(f0.x * 16.f, f0.y * 16.f, h.x, l.x);
            split2(f0.z * 16.f, f0.w * 16.f, h.y, l.y);
            split2(f1.x * 16.f, f1.y * 16.f, h.z, l.z);
            split2(f1.z * 16.f, f1.w * 16.f, h.w, l.w);
            const uint32_t off = SW128(wrow * 128 + wq4 * 32 + g4 * 16);
            *(uint4*)(dh + c * 8192 + off) = h;
            *(uint4*)(dl + c * 8192 + off) = l;
        }
    }
}

// ---------------------------------------------------------------------------
// Projection GEMM via mma.sync fp16 hi/lo; X converted in-kernel (register
// prefetch), W copied raw from precomputed swizzled images.
// Q/K outputs hi/lo split; V output single fp16.
// ---------------------------------------------------------------------------
__global__ __launch_bounds__(256) void proj_kernel(
    const float* __restrict__ Xq, const float* __restrict__ Xk, const float* __restrict__ Xv,
    const float* __restrict__ bq, const float* __restrict__ bk, const float* __restrict__ bv)
{
    __shared__ __align__(128) unsigned char sm[49152];
    // XH @0 (16KB), XL @16384, WH @32768 (8KB), WL @40960

    const float* X; const float* bias;
    const int which = blockIdx.y;
    if (which == 0)      { X = Xq; bias = bq; }
    else if (which == 1) { X = Xk; bias = bk; }
    else                 { X = Xv; bias = bv; }

    const unsigned char* wph = (const unsigned char*)g_Wph + which * 65536;
    const unsigned char* wpl = (const unsigned char*)g_Wpl + which * 65536;

    const int tid = threadIdx.x, lane = tid & 31, wid = tid >> 5;
    const int m0 = blockIdx.x * 128, mw = wid * 16;
    const uint32_t sb = smem_u32(sm);
    const int r8 = lane & 7, sub = lane >> 3;
    const int xrow = tid >> 1, xhalf = tid & 1;

    float acc[8][4];
    #pragma unroll
    for (int n = 0; n < 8; n++)
        #pragma unroll
        for (int e = 0; e < 4; e++) acc[n][e] = 0.f;

    // prefetch chunk 0
    float4 xr[8];
    uint4 wh[2], wl[2];
    {
        const float4* xs = (const float4*)(X + (size_t)(m0 + xrow) * DM + xhalf * 32);
        #pragma unroll
        for (int i = 0; i < 8; i++) xr[i] = xs[i];
        #pragma unroll
        for (int i = 0; i < 2; i++) {
            wh[i] = *(const uint4*)(wph + tid * 32 + i * 16);
            wl[i] = *(const uint4*)(wpl + tid * 32 + i * 16);
        }
    }

    for (int c = 0; c < 8; c++) {
        #pragma unroll
        for (int g4 = 0; g4 < 4; g4++) {
            float4 f0 = xr[g4 * 2], f1 = xr[g4 * 2 + 1];
            uint4 h, l;
            split2(f0.x, f0.y, h.x, l.x); split2(f0.z, f0.w, h.y, l.y);
            split2(f1.x, f1.y, h.z, l.z); split2(f1.z, f1.w, h.w, l.w);
            const uint32_t off = SW128(xrow * 128 + xhalf * 64 + g4 * 16);
            *(uint4*)(sm + off)         = h;
            *(uint4*)(sm + 16384 + off) = l;
        }
        #pragma unroll
        for (int i = 0; i < 2; i++) {
            *(uint4*)(sm + 32768 + tid * 32 + i * 16) = wh[i];
            *(uint4*)(sm + 40960 + tid * 32 + i * 16) = wl[i];
        }
        __syncthreads();

        if (c < 7) {
            const int cn = c + 1;
            const float4* xs = (const float4*)(X + (size_t)(m0 + xrow) * DM + cn * 64 + xhalf * 32);
            #pragma unroll
            for (int i = 0; i < 8; i++) xr[i] = xs[i];
            #pragma unroll
            for (int i = 0; i < 2; i++) {
                wh[i] = *(const uint4*)(wph + cn * 8192 + tid * 32 + i * 16);
                wl[i] = *(const uint4*)(wpl + cn * 8192 + tid * 32 + i * 16);
            }
        }

        uint32_t ah[4][4], al[4][4];
        #pragma unroll
        for (int kk = 0; kk < 4; kk++) {
            const int row = mw + r8 + ((sub & 1) << 3);
            const int byt = kk * 32 + ((sub >> 1) << 4);
            const uint32_t off = SW128(row * 128 + byt);
            LDSM4(ah[kk][0], ah[kk][1], ah[kk][2], ah[kk][3], sb + off);
            LDSM4(al[kk][0], al[kk][1], al[kk][2], al[kk][3], sb + 16384 + off);
        }
        #pragma unroll
        for (int j = 0; j < 4; j++) {
            #pragma unroll
            for (int kk = 0; kk < 4; kk++) {
                const int row = kk * 16 + r8 + ((sub & 1) << 3);
                const int byt = j * 32 + ((sub >> 1) << 4);
                const uint32_t off = SW128(row * 128 + byt);
                uint32_t h0, h1, h2, h3, u0, u1, u2, u3;
                LDSM4T(h0, h1, h2, h3, sb + 32768 + off);
                LDSM4T(u0, u1, u2, u3, sb + 40960 + off);
                MMA(acc[2 * j],     ah[kk], h0, h1);
                MMA(acc[2 * j],     al[kk], h0, h1);
                MMA(acc[2 * j],     ah[kk], u0, u1);
                MMA(acc[2 * j + 1], ah[kk], h2, h3);
                MMA(acc[2 * j + 1], al[kk], h2, h3);
                MMA(acc[2 * j + 1], ah[kk], u2, u3);
            }
        }
        __syncthreads();
    }

    // epilogue: acc/16 + bias; Q/K split hi/lo, V single fp16
    const int g = lane >> 2, cb = (lane & 3) * 2;
    #pragma unroll
    for (int n = 0; n < 8; n++) {
        const int col = n * 8 + cb;
        const float b0 = bias[col], b1 = bias[col + 1];
        const size_t r0 = (size_t)(m0 + mw + g), r1 = r0 + 8;
        const float y00 = acc[n][0] * 0.0625f + b0, y01 = acc[n][1] * 0.0625f + b1;
        const float y10 = acc[n][2] * 0.0625f + b0, y11 = acc[n][3] * 0.0625f + b1;
        if (which == 2) {
            g_Vh[r0 * 32 + (col >> 1)] = pack2(y00, y01);
            g_Vh[r1 * 32 + (col >> 1)] = pack2(y10, y11);
        } else {
            uint32_t* Yh = (which == 0) ? g_Qh : g_Kh;
            uint32_t* Yl = (which == 0) ? g_Ql : g_Kl;
            uint32_t h, l;
            split2(y00, y01, h, l);
            Yh[r0 * 32 + (col >> 1)] = h;  Yl[r0 * 32 + (col >> 1)] = l;
            split2(y10, y11, h, l);
            Yh[r1 * 32 + (col >> 1)] = h;  Yl[r1 * 32 + (col >> 1)] = l;
        }
    }
}

// ---------------------------------------------------------------------------
// Segmented causal flash attention (kv-split), mma.sync fp16.
// GEMM1: 3-term hi/lo (Qh*Kh + Ql*Kh + Qh*Kl), scale applied post-MMA in f32.
// GEMM2: single-term P(fp16) x V(fp16).
// SMEM static 48KB: buf[2] x {KH 8K, KL 8K, VH 8K}; Q staged in buf1 region.
// ---------------------------------------------------------------------------
__global__ void __launch_bounds__(128, 3) attn_kernel(float* __restrict__ out)
{
    __shared__ __align__(128) unsigned char sm[49152];
    const uint32_t sb = smem_u32(sm);

    const int tid = threadIdx.x, lane = tid & 31, wid = tid >> 5;
    const int r8 = lane & 7, sub = lane >> 3;

    // ---- work mapping: longest segments first ----
    const int u = blockIdx.x >> 3, b = blockIdx.x & 7;
    int s, seg;
    if (u < 30)      { s = 31 - u / 3;          seg = u % 3; }
    else if (u < 52) { int v = u - 30; s = 21 - (v >> 1); seg = v & 1; }
    else             { s = 10 - (u - 52);       seg = 0; }
    const int n     = s + 1;
    const int nseg  = (s + 11) / 11;
    const int bse   = n / nseg, rem = n % nseg;
    const int len   = bse + (seg < rem ? 1 : 0);
    const int t0    = seg * bse + (seg < rem ? seg : rem);
    const bool diag = (seg == nseg - 1);

    const int q0   = s * 64;
    const int base = b * SEQ;

    const int row = tid >> 1, half = tid & 1;
    const size_t gtoff = (size_t)row * 32 + half * 16;

    // ---- Q tile -> buf1 region (24576 / 32768), then fragments ----
    {
        const uint4* sh = (const uint4*)(g_Qh + (size_t)(base + q0) * 32 + gtoff);
        const uint4* sl = (const uint4*)(g_Ql + (size_t)(base + q0) * 32 + gtoff);
        #pragma unroll
        for (int g4 = 0; g4 < 4; g4++) {
            const uint32_t off = SW128(row * 128 + half * 64 + g4 * 16);
            *(uint4*)(sm + 24576 + off) = sh[g4];
            *(uint4*)(sm + 32768 + off) = sl[g4];
        }
    }
    __syncthreads();
    uint32_t qh[4][4], ql[4][4];
    #pragma unroll
    for (int kk = 0; kk < 4; kk++) {
        const int qr = wid * 16 + r8 + ((sub & 1) << 3);
        const int byt = kk * 32 + ((sub >> 1) << 4);
        const uint32_t off = SW128(qr * 128 + byt);
        LDSM4(qh[kk][0], qh[kk][1], qh[kk][2], qh[kk][3], sb + 24576 + off);
        LDSM4(ql[kk][0], ql[kk][1], ql[kk][2], ql[kk][3], sb + 32768 + off);
    }

    auto prefetch = [&](int i) {
        const int k0 = (t0 + i) * 64;
        const uint32_t bufb = sb + (uint32_t)(i & 1) * 24576;
        const size_t ge = (size_t)(base + k0) * 32 + gtoff;
        #pragma unroll
        for (int g4 = 0; g4 < 4; g4++) {
            const uint32_t off = SW128(row * 128 + half * 64 + g4 * 16);
            CP16(bufb + off,         g_Kh + ge + g4 * 4);
            CP16(bufb + 8192 + off,  g_Kl + ge + g4 * 4);
            CP16(bufb + 16384 + off, g_Vh + ge + g4 * 4);
        }
        CP_COMMIT();
    };

    prefetch(0);
    __syncthreads();             // all warps done reading Q region (buf1)
    if (len > 1) prefetch(1);

    float od[8][4];
    #pragma unroll
    for (int nn = 0; nn < 8; nn++)
        #pragma unroll
        for (int e = 0; e < 4; e++) od[nn][e] = 0.f;
    float m0v = -1e30f, m1v = -1e30f, l0 = 0.f, l1 = 0.f;

    for (int i = 0; i < len; i++) {
        if (i + 1 < len) { CP_WAIT(1); } else { CP_WAIT(0); }
        __syncthreads();
        const uint32_t bufb = sb + (uint32_t)(i & 1) * 24576;

        // ---- GEMM1: S = Qh*Kh + Ql*Kh + Qh*Kl ----
        float sc[8][4];
        #pragma unroll
        for (int nn = 0; nn < 8; nn++)
            #pragma unroll
            for (int e = 0; e < 4; e++) sc[nn][e] = 0.f;

        #pragma unroll
        for (int j = 0; j < 4; j++) {
            #pragma unroll
            for (int kk = 0; kk < 4; kk++) {
                const int kr = j * 16 + r8 + ((sub & 2) << 2);
                const int byt = kk * 32 + ((sub & 1) << 4);
                const uint32_t off = SW128(kr * 128 + byt);
                uint32_t h0, h1, h2, h3, u0, u1, u2, u3;
                LDSM4(h0, h1, h2, h3, bufb + off);
                LDSM4(u0, u1, u2, u3, bufb + 8192 + off);
                MMA(sc[2 * j],     qh[kk], h0, h1);
                MMA(sc[2 * j],     ql[kk], h0, h1);
                MMA(sc[2 * j],     qh[kk], u0, u1);
                MMA(sc[2 * j + 1], qh[kk], h2, h3);
                MMA(sc[2 * j + 1], ql[kk], h2, h3);
                MMA(sc[2 * j + 1], qh[kk], u2, u3);
            }
        }

        // ---- scale to exp2 domain (in f32, keeps fp16 residuals normal) ----
        #pragma unroll
        for (int nn = 0; nn < 8; nn++)
            #pragma unroll
            for (int e = 0; e < 4; e++) sc[nn][e] *= CEXP;

        // ---- mask (diagonal tile only) ----
        if (diag && i == len - 1) {
            const int cb = (lane & 3) * 2, rl = wid * 16 + (lane >> 2);
            #pragma unroll
            for (int nn = 0; nn < 8; nn++) {
                const int c0 = nn * 8 + cb;
                if (c0     > rl)     sc[nn][0] = -1e30f;
                if (c0 + 1 > rl)     sc[nn][1] = -1e30f;
                if (c0     > rl + 8) sc[nn][2] = -1e30f;
                if (c0 + 1 > rl + 8) sc[nn][3] = -1e30f;
            }
        }

        // ---- online softmax (exp2 domain) ----
        float rm0 = -1e30f, rm1 = -1e30f;
        #pragma unroll
        for (int nn = 0; nn < 8; nn++) {
            rm0 = fmaxf(rm0, fmaxf(sc[nn][0], sc[nn][1]));
            rm1 = fmaxf(rm1, fmaxf(sc[nn][2], sc[nn][3]));
        }
        rm0 = fmaxf(rm0, __shfl_xor_sync(0xffffffffu, rm0, 1));
        rm0 = fmaxf(rm0, __shfl_xor_sync(0xffffffffu, rm0, 2));
        rm1 = fmaxf(rm1, __shfl_xor_sync(0xffffffffu, rm1, 1));
        rm1 = fmaxf(rm1, __shfl_xor_sync(0xffffffffu, rm1, 2));
        const float nm0 = fmaxf(m0v, rm0), nm1 = fmaxf(m1v, rm1);
        const float cor0 = ex2(m0v - nm0), cor1 = ex2(m1v - nm1);
        m0v = nm0; m1v = nm1;

        float rs0 = 0.f, rs1 = 0.f;
        #pragma unroll
        for (int nn = 0; nn < 8; nn++) {
            sc[nn][0] = ex2(sc[nn][0] - nm0); rs0 += sc[nn][0];
            sc[nn][1] = ex2(sc[nn][1] - nm0); rs0 += sc[nn][1];
            sc[nn][2] = ex2(sc[nn][2] - nm1); rs1 += sc[nn][2];
            sc[nn][3] = ex2(sc[nn][3] - nm1); rs1 += sc[nn][3];
        }
        rs0 += __shfl_xor_sync(0xffffffffu, rs0, 1);
        rs0 += __shfl_xor_sync(0xffffffffu, rs0, 2);
        rs1 += __shfl_xor_sync(0xffffffffu, rs1, 1);
        rs1 += __shfl_xor_sync(0xffffffffu, rs1, 2);
        l0 = l0 * cor0 + rs0;
        l1 = l1 * cor1 + rs1;
        #pragma unroll
        for (int nn = 0; nn < 8; nn++) {
            od[nn][0] *= cor0; od[nn][1] *= cor0;
            od[nn][2] *= cor1; od[nn][3] *= cor1;
        }

        // ---- pack P as single-fp16 A-fragments ----
        uint32_t ph[4][4];
        #pragma unroll
        for (int kk = 0; kk < 4; kk++) {
            ph[kk][0] = pack2(sc[2 * kk][0],     sc[2 * kk][1]);
            ph[kk][1] = pack2(sc[2 * kk][2],     sc[2 * kk][3]);
            ph[kk][2] = pack2(sc[2 * kk + 1][0], sc[2 * kk + 1][1]);
            ph[kk][3] = pack2(sc[2 * kk + 1][2], sc[2 * kk + 1][3]);
        }

        // ---- GEMM2: O += P * V (single term) ----
        #pragma unroll
        for (int j = 0; j < 4; j++) {
            #pragma unroll
            for (int kk = 0; kk < 4; kk++) {
                const int vr = kk * 16 + r8 + ((sub & 1) << 3);
                const int byt = j * 32 + ((sub >> 1) << 4);
                const uint32_t off = SW128(vr * 128 + byt);
                uint32_t h0, h1, h2, h3;
                LDSM4T(h0, h1, h2, h3, bufb + 16384 + off);
                MMA(od[2 * j],     ph[kk], h0, h1);
                MMA(od[2 * j + 1], ph[kk], h2, h3);
            }
        }
        __syncthreads();
        if (i + 2 < len) prefetch(i + 2);
    }

    // ---- epilogue ----
    const int g = lane >> 2, cb = (lane & 3) * 2;
    const int lr0 = wid * 16 + g;
    if (nseg == 1) {
        const float inv0 = 1.f / l0, inv1 = 1.f / l1;
        const size_t r0 = (size_t)base + q0 + lr0, r1 = r0 + 8;
        #pragma unroll
        for (int nn = 0; nn < 8; nn++) {
            *(float2*)(out + r0 * DK + nn * 8 + cb) = make_float2(od[nn][0] * inv0, od[nn][1] * inv0);
            *(float2*)(out + r1 * DK + nn * 8 + cb) = make_float2(od[nn][2] * inv1, od[nn][3] * inv1);
        }
    } else {
        const size_t pr0 = ((size_t)seg * NB + b) * SEQ + q0 + lr0, pr1 = pr0 + 8;
        #pragma unroll
        for (int nn = 0; nn < 8; nn++) {
            *(float2*)(g_Op + pr0 * DK + nn * 8 + cb) = make_float2(od[nn][0], od[nn][1]);
            *(float2*)(g_Op + pr1 * DK + nn * 8 + cb) = make_float2(od[nn][2], od[nn][3]);
        }
        if ((lane & 3) == 0) {
            g_Ml[pr0 * 2] = m0v;  g_Ml[pr0 * 2 + 1] = l0;
            g_Ml[pr1 * 2] = m1v;  g_Ml[pr1 * 2 + 1] = l1;
        }
    }
}

// ---------------------------------------------------------------------------
// Combine kv-split partials (rows 704..2047 per batch). 16 threads per row,
// one float4 each -> 4x the parallelism of R8 (was latency-bound at 12us).
// ---------------------------------------------------------------------------
__global__ __launch_bounds__(128) void combine_kernel(float* __restrict__ out)
{
    const int idx = blockIdx.x * 128 + threadIdx.x;     // 8*1344*16 total
    const int q  = idx & 15;
    const int rb = idx >> 4;
    const int row = 704 + (rb % 1344);
    const int b   = rb / 1344;
    const int strip = row >> 6;
    const int nseg  = (strip + 11) / 11;                // 2 or 3

    float mg[3], lg[3];
    float M = -1e30f;
    #pragma unroll 3
    for (int g = 0; g < nseg; g++) {
        const size_t pr = ((size_t)g * NB + b) * SEQ + row;
        const float2 ml = *(const float2*)(g_Ml + pr * 2);
        mg[g] = ml.x;
        lg[g] = ml.y;
        M = fmaxf(M, mg[g]);
    }
    float l = 0.f;
    float4 o = make_float4(0.f, 0.f, 0.f, 0.f);
    #pragma unroll 3
    for (int g = 0; g < nseg; g++) {
        const float w = ex2(mg[g] - M);
        l += lg[g] * w;
        const float4 v = *(const float4*)(g_Op + (((size_t)g * NB + b) * SEQ + row) * DK + q * 4);
        o.x += w * v.x; o.y += w * v.y;
        o.z += w * v.z; o.w += w * v.w;
    }
    const float inv = 1.f / l;
    o.x *= inv; o.y *= inv; o.z *= inv; o.w *= inv;
    *(float4*)(out + ((size_t)b * SEQ + row) * DK + q * 4) = o;
}

// ---------------------------------------------------------------------------
extern "C" void kernel_launch(void* const* d_in, const int* in_sizes, int n_in,
                              void* d_out, int out_size)
{
    (void)in_sizes; (void)n_in; (void)out_size;
    const float* Xq = (const float*)d_in[0];
    const float* Xk = (const float*)d_in[1];
    const float* Xv = (const float*)d_in[2];
    // d_in[3] = mask (analytically causal; not read)
    const float* Wq = (const float*)d_in[4];
    const float* bq = (const float*)d_in[5];
    const float* Wk = (const float*)d_in[6];
    const float* bk = (const float*)d_in[7];
    const float* Wv = (const float*)d_in[8];
    const float* bv = (const float*)d_in[9];
    float* out = (float*)d_out;

    wprep_kernel<<<3, 256>>>(Wq, Wk, Wv);
    proj_kernel<<<dim3(NB * SEQ / 128, 3), 256>>>(Xq, Xk, Xv, bq, bk, bv);
    attn_kernel<<<504, 128>>>(out);
    combine_kernel<<<(NB * 1344 * 16) / 128, 128>>>(out);
}

// round 10
// speedup vs baseline: 8.1031x; 1.0951x over previous
#include <cuda_runtime.h>
#include <cuda_fp16.h>
#include <cstdint>

#define SEQ 2048
#define NB 8
#define DM 512
#define DK 64
#define CEXP 0.18033688011112042f   // (1/sqrt(64)) * log2(e)

// fp16 hi/lo split Q,K (2 fp16 per uint32, low = even col); V single fp16
__device__ uint32_t g_Qh[NB * SEQ * DK / 2], g_Ql[NB * SEQ * DK / 2];
__device__ uint32_t g_Kh[NB * SEQ * DK / 2], g_Kl[NB * SEQ * DK / 2];
__device__ uint32_t g_Vh[NB * SEQ * DK / 2];

// Pre-packed, pre-swizzled (16*W) hi/lo fp16 images: [which][chunk 8][8192 B]
__device__ uint4 g_Wph[3 * 8 * 512], g_Wpl[3 * 8 * 512];

// kv-split partials: [seg 0..2][b][row][dim], and (m,l) pairs
__device__ float g_Op[3 * NB * SEQ * DK];
__device__ float g_Ml[3 * NB * SEQ * 2];
__device__ int   g_cnt[32 * NB];    // zero-init; combiner resets -> replay-safe

#define SW128(x) ((x) ^ (((x) >> 3) & 0x70))

__device__ __forceinline__ uint32_t smem_u32(const void* p) {
    uint32_t a;
    asm("{ .reg .u64 t; cvta.to.shared.u64 t, %1; cvt.u32.u64 %0, t; }" : "=r"(a) : "l"(p));
    return a;
}

// fp16 hi/lo split of two floats
__device__ __forceinline__ void split2(float a, float b, uint32_t& h, uint32_t& l) {
    __half2 H = __floats2half2_rn(a, b);
    float ah = __half2float(__low2half(H));
    float bh = __half2float(__high2half(H));
    __half2 L = __floats2half2_rn(a - ah, b - bh);
    h = *(uint32_t*)&H;
    l = *(uint32_t*)&L;
}
__device__ __forceinline__ uint32_t pack2(float a, float b) {
    __half2 H = __floats2half2_rn(a, b);
    return *(uint32_t*)&H;
}

__device__ __forceinline__ float ex2(float x) {
    float r;
    asm("ex2.approx.f32 %0, %1;" : "=f"(r) : "f"(x));
    return r;
}

#define LDSM4(r0, r1, r2, r3, a) \
    asm volatile("ldmatrix.sync.aligned.m8n8.x4.shared.b16 {%0,%1,%2,%3}, [%4];" \
                 : "=r"(r0), "=r"(r1), "=r"(r2), "=r"(r3) : "r"(a))
#define LDSM4T(r0, r1, r2, r3, a) \
    asm volatile("ldmatrix.sync.aligned.m8n8.x4.trans.shared.b16 {%0,%1,%2,%3}, [%4];" \
                 : "=r"(r0), "=r"(r1), "=r"(r2), "=r"(r3) : "r"(a))
#define MMA(c, a, b0, b1) \
    asm volatile("mma.sync.aligned.m16n8k16.row.col.f32.f16.f16.f32 " \
                 "{%0,%1,%2,%3},{%4,%5,%6,%7},{%8,%9},{%0,%1,%2,%3};" \
                 : "+f"((c)[0]), "+f"((c)[1]), "+f"((c)[2]), "+f"((c)[3]) \
                 : "r"((a)[0]), "r"((a)[1]), "r"((a)[2]), "r"((a)[3]), "r"(b0), "r"(b1))

#define CP16(dst, src) \
    asm volatile("cp.async.cg.shared.global [%0], [%1], 16;" :: "r"(dst), "l"(src))
#define CP_COMMIT() asm volatile("cp.async.commit_group;" ::: "memory")
#define CP_WAIT(n)  asm volatile("cp.async.wait_group %0;" :: "n"(n) : "memory")

// ---------------------------------------------------------------------------
// W prep: 16*W -> fp16 hi/lo pre-swizzled images.
// ---------------------------------------------------------------------------
__global__ __launch_bounds__(256) void wprep_kernel(
    const float* __restrict__ Wq, const float* __restrict__ Wk, const float* __restrict__ Wv)
{
    const int which = blockIdx.x;
    const float* W = (which == 0) ? Wq : (which == 1) ? Wk : Wv;
    const int tid = threadIdx.x;
    const int wrow = tid >> 2, wq4 = tid & 3;
    unsigned char* dh = (unsigned char*)g_Wph + which * 65536;
    unsigned char* dl = (unsigned char*)g_Wpl + which * 65536;

    for (int c = 0; c < 8; c++) {
        const float4* src = (const float4*)(W + (size_t)(c * 64 + wrow) * 64 + wq4 * 16);
        #pragma unroll
        for (int g4 = 0; g4 < 2; g4++) {
            float4 f0 = src[g4 * 2], f1 = src[g4 * 2 + 1];
            uint4 h, l;
            split2(f0.x * 16.f, f0.y * 16.f, h.x, l.x);
            split2(f0.z * 16.f, f0.w * 16.f, h.y, l.y);
            split2(f1.x * 16.f, f1.y * 16.f, h.z, l.z);
            split2(f1.z * 16.f, f1.w * 16.f, h.w, l.w);
            const uint32_t off = SW128(wrow * 128 + wq4 * 32 + g4 * 16);
            *(uint4*)(dh + c * 8192 + off) = h;
            *(uint4*)(dl + c * 8192 + off) = l;
        }
    }
}

// ---------------------------------------------------------------------------
// Projection GEMM via mma.sync fp16 hi/lo.
// X: register prefetch + in-kernel convert. W: raw cp.async (double-buffered)
// from pre-swizzled images -> zero conversion, zero register cost.
// __launch_bounds__(256,2): 2 CTAs/SM (was 1, reg-capped at ~140).
// SMEM (dynamic 64KB): XH@0 16K, XL@16K, Wbuf0@32K {WH,WL}, Wbuf1@48K.
// ---------------------------------------------------------------------------
__global__ void __launch_bounds__(256, 2) proj_kernel(
    const float* __restrict__ Xq, const float* __restrict__ Xk, const float* __restrict__ Xv,
    const float* __restrict__ bq, const float* __restrict__ bk, const float* __restrict__ bv)
{
    extern __shared__ __align__(128) unsigned char sm[];

    const float* X; const float* bias;
    const int which = blockIdx.y;
    if (which == 0)      { X = Xq; bias = bq; }
    else if (which == 1) { X = Xk; bias = bk; }
    else                 { X = Xv; bias = bv; }

    const unsigned char* wph = (const unsigned char*)g_Wph + which * 65536;
    const unsigned char* wpl = (const unsigned char*)g_Wpl + which * 65536;

    const int tid = threadIdx.x, lane = tid & 31, wid = tid >> 5;
    const int m0 = blockIdx.x * 128, mw = wid * 16;
    const uint32_t sb = smem_u32(sm);
    const int r8 = lane & 7, sub = lane >> 3;
    const int xrow = tid >> 1, xhalf = tid & 1;

    float acc[8][4];
    #pragma unroll
    for (int n = 0; n < 8; n++)
        #pragma unroll
        for (int e = 0; e < 4; e++) acc[n][e] = 0.f;

    // W chunk c -> W buffer (c&1): raw async copy of 16KB (WH 8K + WL 8K)
    auto wfetch = [&](int c) {
        const uint32_t wb = sb + 32768 + (uint32_t)(c & 1) * 16384;
        const unsigned char* srch = wph + c * 8192 + tid * 32;
        const unsigned char* srcl = wpl + c * 8192 + tid * 32;
        CP16(wb + tid * 32,            srch);
        CP16(wb + tid * 32 + 16,       srch + 16);
        CP16(wb + 8192 + tid * 32,     srcl);
        CP16(wb + 8192 + tid * 32 + 16, srcl + 16);
        CP_COMMIT();
    };

    // prefetch chunk 0
    wfetch(0);
    float4 xr[8];
    {
        const float4* xs = (const float4*)(X + (size_t)(m0 + xrow) * DM + xhalf * 32);
        #pragma unroll
        for (int i = 0; i < 8; i++) xr[i] = xs[i];
    }

    for (int c = 0; c < 8; c++) {
        // X regs -> split -> SMEM (swizzled)
        #pragma unroll
        for (int g4 = 0; g4 < 4; g4++) {
            float4 f0 = xr[g4 * 2], f1 = xr[g4 * 2 + 1];
            uint4 h, l;
            split2(f0.x, f0.y, h.x, l.x); split2(f0.z, f0.w, h.y, l.y);
            split2(f1.x, f1.y, h.z, l.z); split2(f1.z, f1.w, h.w, l.w);
            const uint32_t off = SW128(xrow * 128 + xhalf * 64 + g4 * 16);
            *(uint4*)(sm + off)         = h;
            *(uint4*)(sm + 16384 + off) = l;
        }

        // prefetch next chunk (W async + X regs), then wait for W(c)
        if (c < 7) {
            const int cn = c + 1;
            wfetch(cn);
            const float4* xs = (const float4*)(X + (size_t)(m0 + xrow) * DM + cn * 64 + xhalf * 32);
            #pragma unroll
            for (int i = 0; i < 8; i++) xr[i] = xs[i];
            CP_WAIT(1);
        } else {
            CP_WAIT(0);
        }
        __syncthreads();

        const uint32_t wb = sb + 32768 + (uint32_t)(c & 1) * 16384;
        uint32_t ah[4][4], al[4][4];
        #pragma unroll
        for (int kk = 0; kk < 4; kk++) {
            const int row = mw + r8 + ((sub & 1) << 3);
            const int byt = kk * 32 + ((sub >> 1) << 4);
            const uint32_t off = SW128(row * 128 + byt);
            LDSM4(ah[kk][0], ah[kk][1], ah[kk][2], ah[kk][3], sb + off);
            LDSM4(al[kk][0], al[kk][1], al[kk][2], al[kk][3], sb + 16384 + off);
        }
        #pragma unroll
        for (int j = 0; j < 4; j++) {
            #pragma unroll
            for (int kk = 0; kk < 4; kk++) {
                const int row = kk * 16 + r8 + ((sub & 1) << 3);
                const int byt = j * 32 + ((sub >> 1) << 4);
                const uint32_t off = SW128(row * 128 + byt);
                uint32_t h0, h1, h2, h3, u0, u1, u2, u3;
                LDSM4T(h0, h1, h2, h3, wb + off);
                LDSM4T(u0, u1, u2, u3, wb + 8192 + off);
                MMA(acc[2 * j],     ah[kk], h0, h1);
                MMA(acc[2 * j],     al[kk], h0, h1);
                MMA(acc[2 * j],     ah[kk], u0, u1);
                MMA(acc[2 * j + 1], ah[kk], h2, h3);
                MMA(acc[2 * j + 1], al[kk], h2, h3);
                MMA(acc[2 * j + 1], ah[kk], u2, u3);
            }
        }
        __syncthreads();
    }

    // epilogue: acc/16 + bias; Q/K split hi/lo, V single fp16
    const int g = lane >> 2, cb = (lane & 3) * 2;
    #pragma unroll
    for (int n = 0; n < 8; n++) {
        const int col = n * 8 + cb;
        const float b0 = bias[col], b1 = bias[col + 1];
        const size_t r0 = (size_t)(m0 + mw + g), r1 = r0 + 8;
        const float y00 = acc[n][0] * 0.0625f + b0, y01 = acc[n][1] * 0.0625f + b1;
        const float y10 = acc[n][2] * 0.0625f + b0, y11 = acc[n][3] * 0.0625f + b1;
        if (which == 2) {
            g_Vh[r0 * 32 + (col >> 1)] = pack2(y00, y01);
            g_Vh[r1 * 32 + (col >> 1)] = pack2(y10, y11);
        } else {
            uint32_t* Yh = (which == 0) ? g_Qh : g_Kh;
            uint32_t* Yl = (which == 0) ? g_Ql : g_Kl;
            uint32_t h, l;
            split2(y00, y01, h, l);
            Yh[r0 * 32 + (col >> 1)] = h;  Yl[r0 * 32 + (col >> 1)] = l;
            split2(y10, y11, h, l);
            Yh[r1 * 32 + (col >> 1)] = h;  Yl[r1 * 32 + (col >> 1)] = l;
        }
    }
}

// ---------------------------------------------------------------------------
// Segmented causal flash attention (kv-split), mma.sync fp16, with FUSED
// combine: last-arriving CTA per (strip,b) merges all segments (atomic
// counter; combiner resets it -> CUDA-graph replay safe; deterministic
// because segment order in the merge is fixed).
// ---------------------------------------------------------------------------
__global__ void __launch_bounds__(128, 3) attn_kernel(float* __restrict__ out)
{
    __shared__ __align__(128) unsigned char sm[49152];
    __shared__ int s_last;
    const uint32_t sb = smem_u32(sm);

    const int tid = threadIdx.x, lane = tid & 31, wid = tid >> 5;
    const int r8 = lane & 7, sub = lane >> 3;

    // ---- work mapping: longest segments first ----
    const int u = blockIdx.x >> 3, b = blockIdx.x & 7;
    int s, seg;
    if (u < 30)      { s = 31 - u / 3;          seg = u % 3; }
    else if (u < 52) { int v = u - 30; s = 21 - (v >> 1); seg = v & 1; }
    else             { s = 10 - (u - 52);       seg = 0; }
    const int n     = s + 1;
    const int nseg  = (s + 11) / 11;
    const int bse   = n / nseg, rem = n % nseg;
    const int len   = bse + (seg < rem ? 1 : 0);
    const int t0    = seg * bse + (seg < rem ? seg : rem);
    const bool diag = (seg == nseg - 1);

    const int q0   = s * 64;
    const int base = b * SEQ;

    const int row = tid >> 1, half = tid & 1;
    const size_t gtoff = (size_t)row * 32 + half * 16;

    // ---- Q tile -> buf1 region (24576 / 32768), then fragments ----
    {
        const uint4* sh = (const uint4*)(g_Qh + (size_t)(base + q0) * 32 + gtoff);
        const uint4* sl = (const uint4*)(g_Ql + (size_t)(base + q0) * 32 + gtoff);
        #pragma unroll
        for (int g4 = 0; g4 < 4; g4++) {
            const uint32_t off = SW128(row * 128 + half * 64 + g4 * 16);
            *(uint4*)(sm + 24576 + off) = sh[g4];
            *(uint4*)(sm + 32768 + off) = sl[g4];
        }
    }
    __syncthreads();
    uint32_t qh[4][4], ql[4][4];
    #pragma unroll
    for (int kk = 0; kk < 4; kk++) {
        const int qr = wid * 16 + r8 + ((sub & 1) << 3);
        const int byt = kk * 32 + ((sub >> 1) << 4);
        const uint32_t off = SW128(qr * 128 + byt);
        LDSM4(qh[kk][0], qh[kk][1], qh[kk][2], qh[kk][3], sb + 24576 + off);
        LDSM4(ql[kk][0], ql[kk][1], ql[kk][2], ql[kk][3], sb + 32768 + off);
    }

    auto prefetch = [&](int i) {
        const int k0 = (t0 + i) * 64;
        const uint32_t bufb = sb + (uint32_t)(i & 1) * 24576;
        const size_t ge = (size_t)(base + k0) * 32 + gtoff;
        #pragma unroll
        for (int g4 = 0; g4 < 4; g4++) {
            const uint32_t off = SW128(row * 128 + half * 64 + g4 * 16);
            CP16(bufb + off,         g_Kh + ge + g4 * 4);
            CP16(bufb + 8192 + off,  g_Kl + ge + g4 * 4);
            CP16(bufb + 16384 + off, g_Vh + ge + g4 * 4);
        }
        CP_COMMIT();
    };

    prefetch(0);
    __syncthreads();             // all warps done reading Q region (buf1)
    if (len > 1) prefetch(1);

    float od[8][4];
    #pragma unroll
    for (int nn = 0; nn < 8; nn++)
        #pragma unroll
        for (int e = 0; e < 4; e++) od[nn][e] = 0.f;
    float m0v = -1e30f, m1v = -1e30f, l0 = 0.f, l1 = 0.f;

    for (int i = 0; i < len; i++) {
        if (i + 1 < len) { CP_WAIT(1); } else { CP_WAIT(0); }
        __syncthreads();
        const uint32_t bufb = sb + (uint32_t)(i & 1) * 24576;

        // ---- GEMM1: S = Qh*Kh + Ql*Kh + Qh*Kl ----
        float sc[8][4];
        #pragma unroll
        for (int nn = 0; nn < 8; nn++)
            #pragma unroll
            for (int e = 0; e < 4; e++) sc[nn][e] = 0.f;

        #pragma unroll
        for (int j = 0; j < 4; j++) {
            #pragma unroll
            for (int kk = 0; kk < 4; kk++) {
                const int kr = j * 16 + r8 + ((sub & 2) << 2);
                const int byt = kk * 32 + ((sub & 1) << 4);
                const uint32_t off = SW128(kr * 128 + byt);
                uint32_t h0, h1, h2, h3, u0, u1, u2, u3;
                LDSM4(h0, h1, h2, h3, bufb + off);
                LDSM4(u0, u1, u2, u3, bufb + 8192 + off);
                MMA(sc[2 * j],     qh[kk], h0, h1);
                MMA(sc[2 * j],     ql[kk], h0, h1);
                MMA(sc[2 * j],     qh[kk], u0, u1);
                MMA(sc[2 * j + 1], qh[kk], h2, h3);
                MMA(sc[2 * j + 1], ql[kk], h2, h3);
                MMA(sc[2 * j + 1], qh[kk], u2, u3);
            }
        }

        // ---- scale to exp2 domain ----
        #pragma unroll
        for (int nn = 0; nn < 8; nn++)
            #pragma unroll
            for (int e = 0; e < 4; e++) sc[nn][e] *= CEXP;

        // ---- mask (diagonal tile only) ----
        if (diag && i == len - 1) {
            const int cb = (lane & 3) * 2, rl = wid * 16 + (lane >> 2);
            #pragma unroll
            for (int nn = 0; nn < 8; nn++) {
                const int c0 = nn * 8 + cb;
                if (c0     > rl)     sc[nn][0] = -1e30f;
                if (c0 + 1 > rl)     sc[nn][1] = -1e30f;
                if (c0     > rl + 8) sc[nn][2] = -1e30f;
                if (c0 + 1 > rl + 8) sc[nn][3] = -1e30f;
            }
        }

        // ---- online softmax (exp2 domain) ----
        float rm0 = -1e30f, rm1 = -1e30f;
        #pragma unroll
        for (int nn = 0; nn < 8; nn++) {
            rm0 = fmaxf(rm0, fmaxf(sc[nn][0], sc[nn][1]));
            rm1 = fmaxf(rm1, fmaxf(sc[nn][2], sc[nn][3]));
        }
        rm0 = fmaxf(rm0, __shfl_xor_sync(0xffffffffu, rm0, 1));
        rm0 = fmaxf(rm0, __shfl_xor_sync(0xffffffffu, rm0, 2));
        rm1 = fmaxf(rm1, __shfl_xor_sync(0xffffffffu, rm1, 1));
        rm1 = fmaxf(rm1, __shfl_xor_sync(0xffffffffu, rm1, 2));
        const float nm0 = fmaxf(m0v, rm0), nm1 = fmaxf(m1v, rm1);
        const float cor0 = ex2(m0v - nm0), cor1 = ex2(m1v - nm1);
        m0v = nm0; m1v = nm1;

        float rs0 = 0.f, rs1 = 0.f;
        #pragma unroll
        for (int nn = 0; nn < 8; nn++) {
            sc[nn][0] = ex2(sc[nn][0] - nm0); rs0 += sc[nn][0];
            sc[nn][1] = ex2(sc[nn][1] - nm0); rs0 += sc[nn][1];
            sc[nn][2] = ex2(sc[nn][2] - nm1); rs1 += sc[nn][2];
            sc[nn][3] = ex2(sc[nn][3] - nm1); rs1 += sc[nn][3];
        }
        rs0 += __shfl_xor_sync(0xffffffffu, rs0, 1);
        rs0 += __shfl_xor_sync(0xffffffffu, rs0, 2);
        rs1 += __shfl_xor_sync(0xffffffffu, rs1, 1);
        rs1 += __shfl_xor_sync(0xffffffffu, rs1, 2);
        l0 = l0 * cor0 + rs0;
        l1 = l1 * cor1 + rs1;
        #pragma unroll
        for (int nn = 0; nn < 8; nn++) {
            od[nn][0] *= cor0; od[nn][1] *= cor0;
            od[nn][2] *= cor1; od[nn][3] *= cor1;
        }

        // ---- pack P as single-fp16 A-fragments ----
        uint32_t ph[4][4];
        #pragma unroll
        for (int kk = 0; kk < 4; kk++) {
            ph[kk][0] = pack2(sc[2 * kk][0],     sc[2 * kk][1]);
            ph[kk][1] = pack2(sc[2 * kk][2],     sc[2 * kk][3]);
            ph[kk][2] = pack2(sc[2 * kk + 1][0], sc[2 * kk + 1][1]);
            ph[kk][3] = pack2(sc[2 * kk + 1][2], sc[2 * kk + 1][3]);
        }

        // ---- GEMM2: O += P * V (single term) ----
        #pragma unroll
        for (int j = 0; j < 4; j++) {
            #pragma unroll
            for (int kk = 0; kk < 4; kk++) {
                const int vr = kk * 16 + r8 + ((sub & 1) << 3);
                const int byt = j * 32 + ((sub >> 1) << 4);
                const uint32_t off = SW128(vr * 128 + byt);
                uint32_t h0, h1, h2, h3;
                LDSM4T(h0, h1, h2, h3, bufb + 16384 + off);
                MMA(od[2 * j],     ph[kk], h0, h1);
                MMA(od[2 * j + 1], ph[kk], h2, h3);
            }
        }
        __syncthreads();
        if (i + 2 < len) prefetch(i + 2);
    }

    // ---- epilogue ----
    const int g = lane >> 2, cb = (lane & 3) * 2;
    const int lr0 = wid * 16 + g;
    if (nseg == 1) {
        const float inv0 = 1.f / l0, inv1 = 1.f / l1;
        const size_t r0 = (size_t)base + q0 + lr0, r1 = r0 + 8;
        #pragma unroll
        for (int nn = 0; nn < 8; nn++) {
            *(float2*)(out + r0 * DK + nn * 8 + cb) = make_float2(od[nn][0] * inv0, od[nn][1] * inv0);
            *(float2*)(out + r1 * DK + nn * 8 + cb) = make_float2(od[nn][2] * inv1, od[nn][3] * inv1);
        }
        return;
    }

    // multi-seg: write partials, then last arriver combines
    {
        const size_t pr0 = ((size_t)seg * NB + b) * SEQ + q0 + lr0, pr1 = pr0 + 8;
        #pragma unroll
        for (int nn = 0; nn < 8; nn++) {
            *(float2*)(g_Op + pr0 * DK + nn * 8 + cb) = make_float2(od[nn][0], od[nn][1]);
            *(float2*)(g_Op + pr1 * DK + nn * 8 + cb) = make_float2(od[nn][2], od[nn][3]);
        }
        if ((lane & 3) == 0) {
            g_Ml[pr0 * 2] = m0v;  g_Ml[pr0 * 2 + 1] = l0;
            g_Ml[pr1 * 2] = m1v;  g_Ml[pr1 * 2 + 1] = l1;
        }
    }
    __syncthreads();
    __threadfence();
    if (tid == 0) {
        const int old = atomicAdd(&g_cnt[s * NB + b], 1);
        s_last = (old == nseg - 1) ? 1 : 0;
    }
    __syncthreads();
    if (!s_last) return;

    // ---- fused combine: this CTA merges all segments for rows q0..q0+63 ----
    __threadfence();
    {
        const int crow = q0 + (tid >> 1);
        const int chalf = tid & 1;
        float mg[3], lg[3];
        float M = -1e30f;
        for (int g2 = 0; g2 < nseg; g2++) {
            const size_t pr = ((size_t)g2 * NB + b) * SEQ + crow;
            const float2 ml = *(const float2*)(g_Ml + pr * 2);
            mg[g2] = ml.x; lg[g2] = ml.y;
            M = fmaxf(M, ml.x);
        }
        float l = 0.f;
        float4 o[8];
        #pragma unroll
        for (int k = 0; k < 8; k++) o[k] = make_float4(0.f, 0.f, 0.f, 0.f);
        for (int g2 = 0; g2 < nseg; g2++) {
            const float w = ex2(mg[g2] - M);
            l += lg[g2] * w;
            const float4* src = (const float4*)(g_Op + (((size_t)g2 * NB + b) * SEQ + crow) * DK + chalf * 32);
            #pragma unroll
            for (int k = 0; k < 8; k++) {
                const float4 v = src[k];
                o[k].x += w * v.x; o[k].y += w * v.y;
                o[k].z += w * v.z; o[k].w += w * v.w;
            }
        }
        const float inv = 1.f / l;
        float4* dst = (float4*)(out + ((size_t)base + crow) * DK + chalf * 32);
        #pragma unroll
        for (int k = 0; k < 8; k++) {
            o[k].x *= inv; o[k].y *= inv; o[k].z *= inv; o[k].w *= inv;
            dst[k] = o[k];
        }
    }
    if (tid == 0) g_cnt[s * NB + b] = 0;   // reset for next graph replay
}

// ---------------------------------------------------------------------------
extern "C" void kernel_launch(void* const* d_in, const int* in_sizes, int n_in,
                              void* d_out, int out_size)
{
    (void)in_sizes; (void)n_in; (void)out_size;
    const float* Xq = (const float*)d_in[0];
    const float* Xk = (const float*)d_in[1];
    const float* Xv = (const float*)d_in[2];
    // d_in[3] = mask (analytically causal; not read)
    const float* Wq = (const float*)d_in[4];
    const float* bq = (const float*)d_in[5];
    const float* Wk = (const float*)d_in[6];
    const float* bk = (const float*)d_in[7];
    const float* Wv = (const float*)d_in[8];
    const float* bv = (const float*)d_in[9];
    float* out = (float*)d_out;

    cudaFuncSetAttribute(proj_kernel, cudaFuncAttributeMaxDynamicSharedMemorySize, 65536);

    wprep_kernel<<<3, 256>>>(Wq, Wk, Wv);
    proj_kernel<<<dim3(NB * SEQ / 128, 3), 256, 65536>>>(Xq, Xk, Xv, bq, bk, bv);
    attn_kernel<<<504, 128>>>(out);
}

// round 11
// speedup vs baseline: 8.7560x; 1.0806x over previous
#include <cuda_runtime.h>
#include <cuda_fp16.h>
#include <cstdint>

#define SEQ 2048
#define NB 8
#define DM 512
#define DK 64
#define CEXP 0.18033688011112042f   // (1/sqrt(64)) * log2(e)

// fp16 hi/lo split Q,K (2 fp16 per uint32, low = even col); V single fp16
__device__ uint32_t g_Qh[NB * SEQ * DK / 2], g_Ql[NB * SEQ * DK / 2];
__device__ uint32_t g_Kh[NB * SEQ * DK / 2], g_Kl[NB * SEQ * DK / 2];
__device__ uint32_t g_Vh[NB * SEQ * DK / 2];

// Pre-packed, pre-swizzled (16*W) hi/lo fp16 images: [which][chunk 8][8192 B]
__device__ uint4 g_Wph[3 * 8 * 512], g_Wpl[3 * 8 * 512];

// kv-split partials: [seg 0..2][b][row][dim], and (m,l) pairs
__device__ float g_Op[3 * NB * SEQ * DK];
__device__ float g_Ml[3 * NB * SEQ * 2];
__device__ int   g_cnt[32 * NB];    // zero-init; combiner resets -> replay-safe

#define SW128(x) ((x) ^ (((x) >> 3) & 0x70))

__device__ __forceinline__ uint32_t smem_u32(const void* p) {
    uint32_t a;
    asm("{ .reg .u64 t; cvta.to.shared.u64 t, %1; cvt.u32.u64 %0, t; }" : "=r"(a) : "l"(p));
    return a;
}

// fp16 hi/lo split of two floats
__device__ __forceinline__ void split2(float a, float b, uint32_t& h, uint32_t& l) {
    __half2 H = __floats2half2_rn(a, b);
    float ah = __half2float(__low2half(H));
    float bh = __half2float(__high2half(H));
    __half2 L = __floats2half2_rn(a - ah, b - bh);
    h = *(uint32_t*)&H;
    l = *(uint32_t*)&L;
}
__device__ __forceinline__ uint32_t pack2(float a, float b) {
    __half2 H = __floats2half2_rn(a, b);
    return *(uint32_t*)&H;
}

__device__ __forceinline__ float ex2(float x) {
    float r;
    asm("ex2.approx.f32 %0, %1;" : "=f"(r) : "f"(x));
    return r;
}

#define LDSM4(r0, r1, r2, r3, a) \
    asm volatile("ldmatrix.sync.aligned.m8n8.x4.shared.b16 {%0,%1,%2,%3}, [%4];" \
                 : "=r"(r0), "=r"(r1), "=r"(r2), "=r"(r3) : "r"(a))
#define LDSM4T(r0, r1, r2, r3, a) \
    asm volatile("ldmatrix.sync.aligned.m8n8.x4.trans.shared.b16 {%0,%1,%2,%3}, [%4];" \
                 : "=r"(r0), "=r"(r1), "=r"(r2), "=r"(r3) : "r"(a))
#define MMA(c, a, b0, b1) \
    asm volatile("mma.sync.aligned.m16n8k16.row.col.f32.f16.f16.f32 " \
                 "{%0,%1,%2,%3},{%4,%5,%6,%7},{%8,%9},{%0,%1,%2,%3};" \
                 : "+f"((c)[0]), "+f"((c)[1]), "+f"((c)[2]), "+f"((c)[3]) \
                 : "r"((a)[0]), "r"((a)[1]), "r"((a)[2]), "r"((a)[3]), "r"(b0), "r"(b1))

#define CP16(dst, src) \
    asm volatile("cp.async.cg.shared.global [%0], [%1], 16;" :: "r"(dst), "l"(src))
#define CP_COMMIT() asm volatile("cp.async.commit_group;" ::: "memory")
#define CP_WAIT(n)  asm volatile("cp.async.wait_group %0;" :: "n"(n) : "memory")

// ---------------------------------------------------------------------------
// W prep: 16*W -> fp16 hi/lo pre-swizzled images.
// 24 CTAs (one per (which, chunk)) — was 3 CTAs / 10.4us, pure latency waste.
// ---------------------------------------------------------------------------
__global__ __launch_bounds__(256) void wprep_kernel(
    const float* __restrict__ Wq, const float* __restrict__ Wk, const float* __restrict__ Wv)
{
    const int which = blockIdx.x >> 3;
    const int c     = blockIdx.x & 7;
    const float* W = (which == 0) ? Wq : (which == 1) ? Wk : Wv;
    const int tid = threadIdx.x;
    const int wrow = tid >> 2, wq4 = tid & 3;
    unsigned char* dh = (unsigned char*)g_Wph + which * 65536 + c * 8192;
    unsigned char* dl = (unsigned char*)g_Wpl + which * 65536 + c * 8192;

    const float4* src = (const float4*)(W + (size_t)(c * 64 + wrow) * 64 + wq4 * 16);
    #pragma unroll
    for (int g4 = 0; g4 < 2; g4++) {
        float4 f0 = src[g4 * 2], f1 = src[g4 * 2 + 1];
        uint4 h, l;
        split2(f0.x * 16.f, f0.y * 16.f, h.x, l.x);
        split2(f0.z * 16.f, f0.w * 16.f, h.y, l.y);
        split2(f1.x * 16.f, f1.y * 16.f, h.z, l.z);
        split2(f1.z * 16.f, f1.w * 16.f, h.w, l.w);
        const uint32_t off = SW128(wrow * 128 + wq4 * 32 + g4 * 16);
        *(uint4*)(dh + off) = h;
        *(uint4*)(dl + off) = l;
    }
}

// ---------------------------------------------------------------------------
// Projection GEMM via mma.sync fp16 hi/lo.
// X: register prefetch + in-kernel convert. W: raw cp.async (double-buffered)
// from pre-swizzled images. 2 CTAs/SM.
// SMEM (dynamic 64KB): XH@0 16K, XL@16K, Wbuf0@32K {WH,WL}, Wbuf1@48K.
// ---------------------------------------------------------------------------
__global__ void __launch_bounds__(256, 2) proj_kernel(
    const float* __restrict__ Xq, const float* __restrict__ Xk, const float* __restrict__ Xv,
    const float* __restrict__ bq, const float* __restrict__ bk, const float* __restrict__ bv)
{
    extern __shared__ __align__(128) unsigned char sm[];

    const float* X; const float* bias;
    const int which = blockIdx.y;
    if (which == 0)      { X = Xq; bias = bq; }
    else if (which == 1) { X = Xk; bias = bk; }
    else                 { X = Xv; bias = bv; }

    const unsigned char* wph = (const unsigned char*)g_Wph + which * 65536;
    const unsigned char* wpl = (const unsigned char*)g_Wpl + which * 65536;

    const int tid = threadIdx.x, lane = tid & 31, wid = tid >> 5;
    const int m0 = blockIdx.x * 128, mw = wid * 16;
    const uint32_t sb = smem_u32(sm);
    const int r8 = lane & 7, sub = lane >> 3;
    const int xrow = tid >> 1, xhalf = tid & 1;

    float acc[8][4];
    #pragma unroll
    for (int n = 0; n < 8; n++)
        #pragma unroll
        for (int e = 0; e < 4; e++) acc[n][e] = 0.f;

    auto wfetch = [&](int c) {
        const uint32_t wb = sb + 32768 + (uint32_t)(c & 1) * 16384;
        const unsigned char* srch = wph + c * 8192 + tid * 32;
        const unsigned char* srcl = wpl + c * 8192 + tid * 32;
        CP16(wb + tid * 32,             srch);
        CP16(wb + tid * 32 + 16,        srch + 16);
        CP16(wb + 8192 + tid * 32,      srcl);
        CP16(wb + 8192 + tid * 32 + 16, srcl + 16);
        CP_COMMIT();
    };

    wfetch(0);
    float4 xr[8];
    {
        const float4* xs = (const float4*)(X + (size_t)(m0 + xrow) * DM + xhalf * 32);
        #pragma unroll
        for (int i = 0; i < 8; i++) xr[i] = xs[i];
    }

    for (int c = 0; c < 8; c++) {
        #pragma unroll
        for (int g4 = 0; g4 < 4; g4++) {
            float4 f0 = xr[g4 * 2], f1 = xr[g4 * 2 + 1];
            uint4 h, l;
            split2(f0.x, f0.y, h.x, l.x); split2(f0.z, f0.w, h.y, l.y);
            split2(f1.x, f1.y, h.z, l.z); split2(f1.z, f1.w, h.w, l.w);
            const uint32_t off = SW128(xrow * 128 + xhalf * 64 + g4 * 16);
            *(uint4*)(sm + off)         = h;
            *(uint4*)(sm + 16384 + off) = l;
        }

        if (c < 7) {
            const int cn = c + 1;
            wfetch(cn);
            const float4* xs = (const float4*)(X + (size_t)(m0 + xrow) * DM + cn * 64 + xhalf * 32);
            #pragma unroll
            for (int i = 0; i < 8; i++) xr[i] = xs[i];
            CP_WAIT(1);
        } else {
            CP_WAIT(0);
        }
        __syncthreads();

        const uint32_t wb = sb + 32768 + (uint32_t)(c & 1) * 16384;
        uint32_t ah[4][4], al[4][4];
        #pragma unroll
        for (int kk = 0; kk < 4; kk++) {
            const int row = mw + r8 + ((sub & 1) << 3);
            const int byt = kk * 32 + ((sub >> 1) << 4);
            const uint32_t off = SW128(row * 128 + byt);
            LDSM4(ah[kk][0], ah[kk][1], ah[kk][2], ah[kk][3], sb + off);
            LDSM4(al[kk][0], al[kk][1], al[kk][2], al[kk][3], sb + 16384 + off);
        }
        #pragma unroll
        for (int j = 0; j < 4; j++) {
            #pragma unroll
            for (int kk = 0; kk < 4; kk++) {
                const int row = kk * 16 + r8 + ((sub & 1) << 3);
                const int byt = j * 32 + ((sub >> 1) << 4);
                const uint32_t off = SW128(row * 128 + byt);
                uint32_t h0, h1, h2, h3, u0, u1, u2, u3;
                LDSM4T(h0, h1, h2, h3, wb + off);
                LDSM4T(u0, u1, u2, u3, wb + 8192 + off);
                MMA(acc[2 * j],     ah[kk], h0, h1);
                MMA(acc[2 * j],     al[kk], h0, h1);
                MMA(acc[2 * j],     ah[kk], u0, u1);
                MMA(acc[2 * j + 1], ah[kk], h2, h3);
                MMA(acc[2 * j + 1], al[kk], h2, h3);
                MMA(acc[2 * j + 1], ah[kk], u2, u3);
            }
        }
        __syncthreads();
    }

    // epilogue: acc/16 + bias; Q/K split hi/lo, V single fp16
    const int g = lane >> 2, cb = (lane & 3) * 2;
    #pragma unroll
    for (int n = 0; n < 8; n++) {
        const int col = n * 8 + cb;
        const float b0 = bias[col], b1 = bias[col + 1];
        const size_t r0 = (size_t)(m0 + mw + g), r1 = r0 + 8;
        const float y00 = acc[n][0] * 0.0625f + b0, y01 = acc[n][1] * 0.0625f + b1;
        const float y10 = acc[n][2] * 0.0625f + b0, y11 = acc[n][3] * 0.0625f + b1;
        if (which == 2) {
            g_Vh[r0 * 32 + (col >> 1)] = pack2(y00, y01);
            g_Vh[r1 * 32 + (col >> 1)] = pack2(y10, y11);
        } else {
            uint32_t* Yh = (which == 0) ? g_Qh : g_Kh;
            uint32_t* Yl = (which == 0) ? g_Ql : g_Kl;
            uint32_t h, l;
            split2(y00, y01, h, l);
            Yh[r0 * 32 + (col >> 1)] = h;  Yl[r0 * 32 + (col >> 1)] = l;
            split2(y10, y11, h, l);
            Yh[r1 * 32 + (col >> 1)] = h;  Yl[r1 * 32 + (col >> 1)] = l;
        }
    }
}

// ---------------------------------------------------------------------------
// Segmented causal flash attention (kv-split), mma.sync fp16, fused combine.
// prefetch(0) issued BEFORE Q staging (disjoint SMEM regions) so the first
// K/V tile's DRAM latency overlaps the Q load + fragment extraction.
// ---------------------------------------------------------------------------
__global__ void __launch_bounds__(128, 3) attn_kernel(float* __restrict__ out)
{
    __shared__ __align__(128) unsigned char sm[49152];
    __shared__ int s_last;
    const uint32_t sb = smem_u32(sm);

    const int tid = threadIdx.x, lane = tid & 31, wid = tid >> 5;
    const int r8 = lane & 7, sub = lane >> 3;

    // ---- work mapping: longest segments first ----
    const int u = blockIdx.x >> 3, b = blockIdx.x & 7;
    int s, seg;
    if (u < 30)      { s = 31 - u / 3;          seg = u % 3; }
    else if (u < 52) { int v = u - 30; s = 21 - (v >> 1); seg = v & 1; }
    else             { s = 10 - (u - 52);       seg = 0; }
    const int n     = s + 1;
    const int nseg  = (s + 11) / 11;
    const int bse   = n / nseg, rem = n % nseg;
    const int len   = bse + (seg < rem ? 1 : 0);
    const int t0    = seg * bse + (seg < rem ? seg : rem);
    const bool diag = (seg == nseg - 1);

    const int q0   = s * 64;
    const int base = b * SEQ;

    const int row = tid >> 1, half = tid & 1;
    const size_t gtoff = (size_t)row * 32 + half * 16;

    auto prefetch = [&](int i) {
        const int k0 = (t0 + i) * 64;
        const uint32_t bufb = sb + (uint32_t)(i & 1) * 24576;
        const size_t ge = (size_t)(base + k0) * 32 + gtoff;
        #pragma unroll
        for (int g4 = 0; g4 < 4; g4++) {
            const uint32_t off = SW128(row * 128 + half * 64 + g4 * 16);
            CP16(bufb + off,         g_Kh + ge + g4 * 4);
            CP16(bufb + 8192 + off,  g_Kl + ge + g4 * 4);
            CP16(bufb + 16384 + off, g_Vh + ge + g4 * 4);
        }
        CP_COMMIT();
    };

    // pf(0) targets buf0 (0..24575); Q staging targets buf1 (24576..40960)
    // -> disjoint, so start the K/V fetch before Q is even loaded.
    prefetch(0);

    // ---- Q tile -> buf1 region (24576 / 32768), then fragments ----
    {
        const uint4* sh = (const uint4*)(g_Qh + (size_t)(base + q0) * 32 + gtoff);
        const uint4* sl = (const uint4*)(g_Ql + (size_t)(base + q0) * 32 + gtoff);
        #pragma unroll
        for (int g4 = 0; g4 < 4; g4++) {
            const uint32_t off = SW128(row * 128 + half * 64 + g4 * 16);
            *(uint4*)(sm + 24576 + off) = sh[g4];
            *(uint4*)(sm + 32768 + off) = sl[g4];
        }
    }
    __syncthreads();
    uint32_t qh[4][4], ql[4][4];
    #pragma unroll
    for (int kk = 0; kk < 4; kk++) {
        const int qr = wid * 16 + r8 + ((sub & 1) << 3);
        const int byt = kk * 32 + ((sub >> 1) << 4);
        const uint32_t off = SW128(qr * 128 + byt);
        LDSM4(qh[kk][0], qh[kk][1], qh[kk][2], qh[kk][3], sb + 24576 + off);
        LDSM4(ql[kk][0], ql[kk][1], ql[kk][2], ql[kk][3], sb + 32768 + off);
    }
    __syncthreads();             // all warps done reading Q region (buf1)
    if (len > 1) prefetch(1);

    float od[8][4];
    #pragma unroll
    for (int nn = 0; nn < 8; nn++)
        #pragma unroll
        for (int e = 0; e < 4; e++) od[nn][e] = 0.f;
    float m0v = -1e30f, m1v = -1e30f, l0 = 0.f, l1 = 0.f;

    for (int i = 0; i < len; i++) {
        if (i + 1 < len) { CP_WAIT(1); } else { CP_WAIT(0); }
        __syncthreads();
        const uint32_t bufb = sb + (uint32_t)(i & 1) * 24576;

        // ---- GEMM1: S = Qh*Kh + Ql*Kh + Qh*Kl ----
        float sc[8][4];
        #pragma unroll
        for (int nn = 0; nn < 8; nn++)
            #pragma unroll
            for (int e = 0; e < 4; e++) sc[nn][e] = 0.f;

        #pragma unroll
        for (int j = 0; j < 4; j++) {
            #pragma unroll
            for (int kk = 0; kk < 4; kk++) {
                const int kr = j * 16 + r8 + ((sub & 2) << 2);
                const int byt = kk * 32 + ((sub & 1) << 4);
                const uint32_t off = SW128(kr * 128 + byt);
                uint32_t h0, h1, h2, h3, u0, u1, u2, u3;
                LDSM4(h0, h1, h2, h3, bufb + off);
                LDSM4(u0, u1, u2, u3, bufb + 8192 + off);
                MMA(sc[2 * j],     qh[kk], h0, h1);
                MMA(sc[2 * j],     ql[kk], h0, h1);
                MMA(sc[2 * j],     qh[kk], u0, u1);
                MMA(sc[2 * j + 1], qh[kk], h2, h3);
                MMA(sc[2 * j + 1], ql[kk], h2, h3);
                MMA(sc[2 * j + 1], qh[kk], u2, u3);
            }
        }

        // ---- scale to exp2 domain ----
        #pragma unroll
        for (int nn = 0; nn < 8; nn++)
            #pragma unroll
            for (int e = 0; e < 4; e++) sc[nn][e] *= CEXP;

        // ---- mask (diagonal tile only) ----
        if (diag && i == len - 1) {
            const int cb = (lane & 3) * 2, rl = wid * 16 + (lane >> 2);
            #pragma unroll
            for (int nn = 0; nn < 8; nn++) {
                const int c0 = nn * 8 + cb;
                if (c0     > rl)     sc[nn][0] = -1e30f;
                if (c0 + 1 > rl)     sc[nn][1] = -1e30f;
                if (c0     > rl + 8) sc[nn][2] = -1e30f;
                if (c0 + 1 > rl + 8) sc[nn][3] = -1e30f;
            }
        }

        // ---- online softmax (exp2 domain) ----
        float rm0 = -1e30f, rm1 = -1e30f;
        #pragma unroll
        for (int nn = 0; nn < 8; nn++) {
            rm0 = fmaxf(rm0, fmaxf(sc[nn][0], sc[nn][1]));
            rm1 = fmaxf(rm1, fmaxf(sc[nn][2], sc[nn][3]));
        }
        rm0 = fmaxf(rm0, __shfl_xor_sync(0xffffffffu, rm0, 1));
        rm0 = fmaxf(rm0, __shfl_xor_sync(0xffffffffu, rm0, 2));
        rm1 = fmaxf(rm1, __shfl_xor_sync(0xffffffffu, rm1, 1));
        rm1 = fmaxf(rm1, __shfl_xor_sync(0xffffffffu, rm1, 2));
        const float nm0 = fmaxf(m0v, rm0), nm1 = fmaxf(m1v, rm1);
        const float cor0 = ex2(m0v - nm0), cor1 = ex2(m1v - nm1);
        m0v = nm0; m1v = nm1;

        float rs0 = 0.f, rs1 = 0.f;
        #pragma unroll
        for (int nn = 0; nn < 8; nn++) {
            sc[nn][0] = ex2(sc[nn][0] - nm0); rs0 += sc[nn][0];
            sc[nn][1] = ex2(sc[nn][1] - nm0); rs0 += sc[nn][1];
            sc[nn][2] = ex2(sc[nn][2] - nm1); rs1 += sc[nn][2];
            sc[nn][3] = ex2(sc[nn][3] - nm1); rs1 += sc[nn][3];
        }
        rs0 += __shfl_xor_sync(0xffffffffu, rs0, 1);
        rs0 += __shfl_xor_sync(0xffffffffu, rs0, 2);
        rs1 += __shfl_xor_sync(0xffffffffu, rs1, 1);
        rs1 += __shfl_xor_sync(0xffffffffu, rs1, 2);
        l0 = l0 * cor0 + rs0;
        l1 = l1 * cor1 + rs1;
        #pragma unroll
        for (int nn = 0; nn < 8; nn++) {
            od[nn][0] *= cor0; od[nn][1] *= cor0;
            od[nn][2] *= cor1; od[nn][3] *= cor1;
        }

        // ---- pack P as single-fp16 A-fragments ----
        uint32_t ph[4][4];
        #pragma unroll
        for (int kk = 0; kk < 4; kk++) {
            ph[kk][0] = pack2(sc[2 * kk][0],     sc[2 * kk][1]);
            ph[kk][1] = pack2(sc[2 * kk][2],     sc[2 * kk][3]);
            ph[kk][2] = pack2(sc[2 * kk + 1][0], sc[2 * kk + 1][1]);
            ph[kk][3] = pack2(sc[2 * kk + 1][2], sc[2 * kk + 1][3]);
        }

        // ---- GEMM2: O += P * V (single term) ----
        #pragma unroll
        for (int j = 0; j < 4; j++) {
            #pragma unroll
            for (int kk = 0; kk < 4; kk++) {
                const int vr = kk * 16 + r8 + ((sub & 1) << 3);
                const int byt = j * 32 + ((sub >> 1) << 4);
                const uint32_t off = SW128(vr * 128 + byt);
                uint32_t h0, h1, h2, h3;
                LDSM4T(h0, h1, h2, h3, bufb + 16384 + off);
                MMA(od[2 * j],     ph[kk], h0, h1);
                MMA(od[2 * j + 1], ph[kk], h2, h3);
            }
        }
        __syncthreads();
        if (i + 2 < len) prefetch(i + 2);
    }

    // ---- epilogue ----
    const int g = lane >> 2, cb = (lane & 3) * 2;
    const int lr0 = wid * 16 + g;
    if (nseg == 1) {
        const float inv0 = 1.f / l0, inv1 = 1.f / l1;
        const size_t r0 = (size_t)base + q0 + lr0, r1 = r0 + 8;
        #pragma unroll
        for (int nn = 0; nn < 8; nn++) {
            *(float2*)(out + r0 * DK + nn * 8 + cb) = make_float2(od[nn][0] * inv0, od[nn][1] * inv0);
            *(float2*)(out + r1 * DK + nn * 8 + cb) = make_float2(od[nn][2] * inv1, od[nn][3] * inv1);
        }
        return;
    }

    // multi-seg: write partials, then last arriver combines
    {
        const size_t pr0 = ((size_t)seg * NB + b) * SEQ + q0 + lr0, pr1 = pr0 + 8;
        #pragma unroll
        for (int nn = 0; nn < 8; nn++) {
            *(float2*)(g_Op + pr0 * DK + nn * 8 + cb) = make_float2(od[nn][0], od[nn][1]);
            *(float2*)(g_Op + pr1 * DK + nn * 8 + cb) = make_float2(od[nn][2], od[nn][3]);
        }
        if ((lane & 3) == 0) {
            g_Ml[pr0 * 2] = m0v;  g_Ml[pr0 * 2 + 1] = l0;
            g_Ml[pr1 * 2] = m1v;  g_Ml[pr1 * 2 + 1] = l1;
        }
    }
    __syncthreads();
    __threadfence();
    if (tid == 0) {
        const int old = atomicAdd(&g_cnt[s * NB + b], 1);
        s_last = (old == nseg - 1) ? 1 : 0;
    }
    __syncthreads();
    if (!s_last) return;

    // ---- fused combine: this CTA merges all segments for rows q0..q0+63 ----
    __threadfence();
    {
        const int crow = q0 + (tid >> 1);
        const int chalf = tid & 1;
        float mg[3], lg[3];
        float M = -1e30f;
        for (int g2 = 0; g2 < nseg; g2++) {
            const size_t pr = ((size_t)g2 * NB + b) * SEQ + crow;
            const float2 ml = *(const float2*)(g_Ml + pr * 2);
            mg[g2] = ml.x; lg[g2] = ml.y;
            M = fmaxf(M, ml.x);
        }
        float l = 0.f;
        float4 o[8];
        #pragma unroll
        for (int k = 0; k < 8; k++) o[k] = make_float4(0.f, 0.f, 0.f, 0.f);
        for (int g2 = 0; g2 < nseg; g2++) {
            const float w = ex2(mg[g2] - M);
            l += lg[g2] * w;
            const float4* src = (const float4*)(g_Op + (((size_t)g2 * NB + b) * SEQ + crow) * DK + chalf * 32);
            #pragma unroll
            for (int k = 0; k < 8; k++) {
                const float4 v = src[k];
                o[k].x += w * v.x; o[k].y += w * v.y;
                o[k].z += w * v.z; o[k].w += w * v.w;
            }
        }
        const float inv = 1.f / l;
        float4* dst = (float4*)(out + ((size_t)base + crow) * DK + chalf * 32);
        #pragma unroll
        for (int k = 0; k < 8; k++) {
            o[k].x *= inv; o[k].y *= inv; o[k].z *= inv; o[k].w *= inv;
            dst[k] = o[k];
        }
    }
    if (tid == 0) g_cnt[s * NB + b] = 0;   // reset for next graph replay
}

// ---------------------------------------------------------------------------
extern "C" void kernel_launch(void* const* d_in, const int* in_sizes, int n_in,
                              void* d_out, int out_size)
{
    (void)in_sizes; (void)n_in; (void)out_size;
    const float* Xq = (const float*)d_in[0];
    const float* Xk = (const float*)d_in[1];
    const float* Xv = (const float*)d_in[2];
    // d_in[3] = mask (analytically causal; not read)
    const float* Wq = (const float*)d_in[4];
    const float* bq = (const float*)d_in[5];
    const float* Wk = (const float*)d_in[6];
    const float* bk = (const float*)d_in[7];
    const float* Wv = (const float*)d_in[8];
    const float* bv = (const float*)d_in[9];
    float* out = (float*)d_out;

    cudaFuncSetAttribute(proj_kernel, cudaFuncAttributeMaxDynamicSharedMemorySize, 65536);

    wprep_kernel<<<24, 256>>>(Wq, Wk, Wv);
    proj_kernel<<<dim3(NB * SEQ / 128, 3), 256, 65536>>>(Xq, Xk, Xv, bq, bk, bv);
    attn_kernel<<<504, 128>>>(out);
}